// round 15
// baseline (speedup 1.0000x reference)
#include <cuda_runtime.h>
#include <cuda_fp16.h>
#include <math.h>
#include <stdint.h>

#define N_ELEM 4194304  // 4*1024*1024

// ---------------- scratch (device globals) ----------------------------------
__device__ float  g_q [N_ELEM];
__device__ float  g_kT[N_ELEM];
__device__ float  g_v [N_ELEM];
__device__ float  g_o2[N_ELEM];
__device__ float  g_t1[N_ELEM];
__device__ float  g_fc1[4096 * 2048];
__device__ double g_bstat[4][2];   // {sum, sumsq} per batch
__device__ float  g_stats[4][2];   // {mean, invstd}
__device__ __align__(16) __half g_ws[25165824];  // weight planes [2][N][K]

#define OFF_WQ1 0
#define OFF_WK1 2097152
#define OFF_WV1 4194304
#define OFF_WO1 6291456
#define OFF_WQ2 8388608
#define OFF_WK2 10485760
#define OFF_WV2 12582912
#define OFF_WO2 14680064
#define OFF_W1  16777216
#define OFF_W2  20971520

// ---------------- PTX helpers -------------------------------------------------
__device__ __forceinline__ void mma_f16(float* c, const unsigned* a, const unsigned* b) {
    asm volatile(
        "mma.sync.aligned.m16n8k16.row.col.f32.f16.f16.f32 "
        "{%0,%1,%2,%3}, {%4,%5,%6,%7}, {%8,%9}, {%0,%1,%2,%3};\n"
        : "+f"(c[0]), "+f"(c[1]), "+f"(c[2]), "+f"(c[3])
        : "r"(a[0]), "r"(a[1]), "r"(a[2]), "r"(a[3]), "r"(b[0]), "r"(b[1]));
}
__device__ __forceinline__ unsigned pack_h2(float a, float b) {
    __half2 h = __floats2half2_rn(a, b);
    return *(unsigned*)&h;
}
__device__ __forceinline__ void ldsm4(unsigned* r, uint32_t a) {
    asm volatile("ldmatrix.sync.aligned.m8n8.x4.shared.b16 {%0,%1,%2,%3}, [%4];"
        : "=r"(r[0]), "=r"(r[1]), "=r"(r[2]), "=r"(r[3]) : "r"(a));
}
__device__ __forceinline__ void cp16(uint32_t dst, const void* src) {
    asm volatile("cp.async.cg.shared.global [%0], [%1], 16;" :: "r"(dst), "l"(src));
}
#define CP_COMMIT() asm volatile("cp.async.commit_group;" ::: "memory")
#define CP_WAIT0()  asm volatile("cp.async.wait_group 0;" ::: "memory")

// A-load with optional fused LayerNorm apply (K must be 1024 when LNIN)
template<bool LNIN>
__device__ __forceinline__ float4 ldA(const float* __restrict__ A,
                                      const float* __restrict__ lnw,
                                      const float* __restrict__ lnb,
                                      int m, int kcol, int K)
{
    float4 av = *(const float4*)(A + (size_t)m * K + kcol);
    if (LNIN) {
        const int b = m >> 10;
        const float mean = g_stats[b][0], inv = g_stats[b][1];
        const size_t wi = ((size_t)m * K + kcol) & 1048575;
        float4 wv = *(const float4*)(lnw + wi);
        float4 bv = *(const float4*)(lnb + wi);
        av.x = (av.x - mean) * inv * wv.x + bv.x;
        av.y = (av.y - mean) * inv * wv.y + bv.y;
        av.z = (av.z - mean) * inv * wv.z + bv.z;
        av.w = (av.w - mean) * inv * wv.w + bv.w;
    }
    return av;
}

// ---------------- weight transpose + 2-way fp16 split ------------------------
struct W8Pack { const float* w[8]; };

__device__ __forceinline__ void wsplit_body(const float* __restrict__ W,
                                            __half* __restrict__ out,
                                            int N, int K, bool proj,
                                            int n0, int k0, int tid)
{
    __shared__ float t[64][65];
#pragma unroll
    for (int r = 0; r < 4; r++) {
        const int flat = tid + (r << 8);
        const int kr = flat >> 4, nc = (flat & 15) << 2;
        const float* src;
        if (proj) src = W + ((size_t)((n0 + nc) >> 6) << 16) + ((size_t)(k0 + kr) << 6) + ((n0 + nc) & 63);
        else      src = W + (size_t)(k0 + kr) * N + n0 + nc;
        float4 v = *(const float4*)src;
        t[kr][nc] = v.x; t[kr][nc + 1] = v.y; t[kr][nc + 2] = v.z; t[kr][nc + 3] = v.w;
    }
    __syncthreads();
    const size_t ps = (size_t)N * K;
#pragma unroll
    for (int r = 0; r < 4; r++) {
        const int flat = tid + (r << 8);
        const int nr = flat >> 4, kc = (flat & 15) << 2;
        unsigned short u0[4], u1[4];
#pragma unroll
        for (int j = 0; j < 4; j++) {
            float x = t[kc + j][nr];
            __half h0 = __float2half_rn(x);
            float r1 = x - __half2float(h0);
            u0[j] = __half_as_ushort(h0);
            u1[j] = __half_as_ushort(__float2half_rn(r1));
        }
        const size_t dst = (size_t)(n0 + nr) * K + k0 + kc;
        *(uint2*)(out + dst)      = make_uint2(u0[0] | (u0[1] << 16), u0[2] | (u0[3] << 16));
        *(uint2*)(out + ps + dst) = make_uint2(u1[0] | (u1[1] << 16), u1[2] | (u1[3] << 16));
    }
}

__global__ __launch_bounds__(256)
void wsplit8_kernel(W8Pack pk, __half* __restrict__ out)
{
    const int z = blockIdx.z;
    const bool proj = (z & 3) != 3;
    wsplit_body(pk.w[z], out + (size_t)z * 2097152, 1024, 1024, proj,
                blockIdx.x << 6, blockIdx.y << 6, threadIdx.x);
}

__global__ __launch_bounds__(256)
void wsplit_kernel(const float* __restrict__ W, __half* __restrict__ out, int N, int K)
{
    wsplit_body(W, out, N, K, false, blockIdx.x << 6, blockIdx.y << 6, threadIdx.x);
}

__global__ void clear_stats_kernel()
{
    if (threadIdx.x < 8) ((double*)g_bstat)[threadIdx.x] = 0.0;
}

// ---------------- GEMM core (shared mainloop) ---------------------------------
struct ProjJob { const __half* Bp; float* C; int mode; };  // mode 0 std, 1 kT
struct ProjPack { ProjJob j[3]; };

template<bool LNIN>
__device__ __forceinline__ void gemm_mainloop(
    const float* __restrict__ A, const __half* __restrict__ Bp,
    const float* __restrict__ lnw, const float* __restrict__ lnb,
    __half* smp, uint32_t sbase, float acc[4][4][4],
    int m0, int n0, int N, int K, int tid, int wm, int wn, int aoff, int boff)
{
    const size_t bstride = (size_t)N * K;
    const int nstage = K >> 5;

    // ---- prologue: B(0) via cp.async, A(0) direct ----
#pragma unroll
    for (int p = 0; p < 2; p++)
#pragma unroll
        for (int r = 0; r < 2; r++) {
            const int flat = tid + (r << 8);
            const int row = flat >> 2, cs = (flat & 3) << 3;
            cp16(sbase + 20480 + p * 10240 + ((row * 40 + cs) << 1),
                 Bp + (size_t)p * bstride + (size_t)(n0 + row) * K + cs);
        }
    CP_COMMIT();
#pragma unroll
    for (int r = 0; r < 4; r++) {
        const int flat = tid + (r << 8);
        const int row = flat >> 3, c4 = (flat & 7) << 2;
        float4 av = ldA<LNIN>(A, lnw, lnb, m0 + row, c4, K);
        float x[4] = {av.x, av.y, av.z, av.w};
        unsigned short u0[4], u1[4];
#pragma unroll
        for (int j = 0; j < 4; j++) {
            __half h0 = __float2half_rn(x[j]);
            float r1 = x[j] - __half2float(h0);
            u0[j] = __half_as_ushort(h0);
            u1[j] = __half_as_ushort(__float2half_rn(r1));
        }
        const int off = row * 40 + c4;
        *(uint2*)(smp + off)        = make_uint2(u0[0] | (u0[1] << 16), u0[2] | (u0[3] << 16));
        *(uint2*)(smp + 5120 + off) = make_uint2(u1[0] | (u1[1] << 16), u1[2] | (u1[3] << 16));
    }

    for (int s = 0; s < nstage; s++) {
        const uint32_t stg = (uint32_t)(s & 1) * 40960u;
        CP_WAIT0();
        __syncthreads();

        float4 pa2[4];
        const int kn = (s + 1) << 5;
        const bool more = kn < K;
        if (more) {
            const uint32_t nst = (uint32_t)((s + 1) & 1) * 40960u;
#pragma unroll
            for (int p = 0; p < 2; p++)
#pragma unroll
                for (int r = 0; r < 2; r++) {
                    const int flat = tid + (r << 8);
                    const int row = flat >> 2, cs = (flat & 3) << 3;
                    cp16(sbase + nst + 20480 + p * 10240 + ((row * 40 + cs) << 1),
                         Bp + (size_t)p * bstride + (size_t)(n0 + row) * K + kn + cs);
                }
            CP_COMMIT();
#pragma unroll
            for (int r = 0; r < 4; r++) {
                const int flat = tid + (r << 8);
                const int row = flat >> 3, c4 = (flat & 7) << 2;
                pa2[r] = ldA<LNIN>(A, lnw, lnb, m0 + row, kn + c4, K);
            }
        }

        const uint32_t Ab = sbase + stg;
        const uint32_t Bb = sbase + stg + 20480;
#pragma unroll
        for (int kt = 0; kt < 2; kt++) {
            const int kbB = kt << 5;
            unsigned a0[4][4], b0[4][2], bx[4][2], a1[4][4];
#pragma unroll
            for (int mt = 0; mt < 4; mt++)
                ldsm4(a0[mt], Ab + ((((wm << 6) + (mt << 4)) * 40) << 1) + kbB + aoff);
#pragma unroll
            for (int nh = 0; nh < 2; nh++) {
                unsigned t4[4];
                ldsm4(t4, Bb + ((((wn << 5) + (nh << 4)) * 40) << 1) + kbB + boff);
                b0[2 * nh][0] = t4[0]; b0[2 * nh][1] = t4[1];
                b0[2 * nh + 1][0] = t4[2]; b0[2 * nh + 1][1] = t4[3];
            }
#pragma unroll
            for (int mt = 0; mt < 4; mt++)
#pragma unroll
                for (int nt = 0; nt < 4; nt++)
                    mma_f16(acc[mt][nt], a0[mt], b0[nt]);   // Ah*Bh
#pragma unroll
            for (int nh = 0; nh < 2; nh++) {
                unsigned t4[4];
                ldsm4(t4, Bb + 10240 + ((((wn << 5) + (nh << 4)) * 40) << 1) + kbB + boff);
                bx[2 * nh][0] = t4[0]; bx[2 * nh][1] = t4[1];
                bx[2 * nh + 1][0] = t4[2]; bx[2 * nh + 1][1] = t4[3];
            }
#pragma unroll
            for (int mt = 0; mt < 4; mt++)
#pragma unroll
                for (int nt = 0; nt < 4; nt++)
                    mma_f16(acc[mt][nt], a0[mt], bx[nt]);   // Ah*Bl
#pragma unroll
            for (int mt = 0; mt < 4; mt++)
                ldsm4(a1[mt], Ab + 10240 + ((((wm << 6) + (mt << 4)) * 40) << 1) + kbB + aoff);
#pragma unroll
            for (int mt = 0; mt < 4; mt++)
#pragma unroll
                for (int nt = 0; nt < 4; nt++)
                    mma_f16(acc[mt][nt], a1[mt], b0[nt]);   // Al*Bh
        }

        if (more) {
            __half* An = smp + ((s + 1) & 1) * 20480;
#pragma unroll
            for (int r = 0; r < 4; r++) {
                const int flat = tid + (r << 8);
                const int row = flat >> 3, c4 = (flat & 7) << 2;
                float x[4] = {pa2[r].x, pa2[r].y, pa2[r].z, pa2[r].w};
                unsigned short u0[4], u1[4];
#pragma unroll
                for (int j = 0; j < 4; j++) {
                    __half h0 = __float2half_rn(x[j]);
                    float r1 = x[j] - __half2float(h0);
                    u0[j] = __half_as_ushort(h0);
                    u1[j] = __half_as_ushort(__float2half_rn(r1));
                }
                const int off = row * 40 + c4;
                *(uint2*)(An + off)        = make_uint2(u0[0] | (u0[1] << 16), u0[2] | (u0[3] << 16));
                *(uint2*)(An + 5120 + off) = make_uint2(u1[0] | (u1[1] << 16), u1[2] | (u1[3] << 16));
            }
        }
    }
}

// ---------------- fused multi-projection GEMM (z selects weight/output) ------
template<bool LNIN>
__global__ __launch_bounds__(256, 2)
void hf_gemm_proj(const float* __restrict__ A, ProjPack pk, int K,
                  const float* __restrict__ lnw, const float* __restrict__ lnb)
{
    extern __shared__ __half smp[];
    const uint32_t sbase = (uint32_t)__cvta_generic_to_shared(smp);
    const int tid  = threadIdx.x;
    const int lane = tid & 31, wid = tid >> 5;
    const int g = lane >> 2, tig = lane & 3;
    const int quad = lane >> 3, rr = lane & 7;
    const int wm = wid >> 2, wn = wid & 3;
    const int m0 = blockIdx.y << 7, n0 = blockIdx.x << 7;
    const int aoff = ((rr + ((quad & 1) << 3)) * 40 + ((quad >> 1) << 3)) << 1;
    const int boff = ((rr + ((quad >> 1) << 3)) * 40 + ((quad & 1) << 3)) << 1;
    const ProjJob job = pk.j[blockIdx.z];

    float acc[4][4][4];
#pragma unroll
    for (int mt = 0; mt < 4; mt++)
#pragma unroll
        for (int nt = 0; nt < 4; nt++)
#pragma unroll
            for (int c = 0; c < 4; c++) acc[mt][nt][c] = 0.f;

    gemm_mainloop<LNIN>(A, job.Bp, lnw, lnb, smp, sbase, acc, m0, n0, 1024, K, tid, wm, wn, aoff, boff);

    float* C = job.C;
    if (job.mode == 0) {
#pragma unroll
        for (int mt = 0; mt < 4; mt++)
#pragma unroll
            for (int nt = 0; nt < 4; nt++) {
                const int m = m0 + (wm << 6) + (mt << 4) + g;
                const int n = n0 + (wn << 5) + (nt << 3) + (tig << 1);
                const float* c = acc[mt][nt];
                const int b = m >> 10, s = m & 1023;
                const int h = n >> 6, d = n & 63;
                const size_t hb = (size_t)(h * 4 + b);
                *(float2*)(C + (((hb << 10) + s) << 6) + d) = make_float2(c[0], c[1]);
                *(float2*)(C + (((hb << 10) + s + 8) << 6) + d) = make_float2(c[2], c[3]);
            }
    } else {
#pragma unroll
        for (int mt = 0; mt < 4; mt++)
#pragma unroll
            for (int nt = 0; nt < 4; nt++) {
                const int m = m0 + (wm << 6) + (mt << 4) + g;
                const int n = n0 + (wn << 5) + (nt << 3) + (tig << 1);
                const float* c = acc[mt][nt];
                const int b = m >> 10, s = m & 1023;
                const int h = n >> 6, d = n & 63;
                const size_t hb = (size_t)(h * 4 + b);
                const int t0a = ((s & 15) << 6) | d;
                const int t0b = (((s + 8) & 15) << 6) | d;
                C[((hb << 10) + t0a)     * 64 + (s >> 4)]       = c[0];
                C[((hb << 10) + t0a + 1) * 64 + (s >> 4)]       = c[1];
                C[((hb << 10) + t0b)     * 64 + ((s + 8) >> 4)] = c[2];
                C[((hb << 10) + t0b + 1) * 64 + ((s + 8) >> 4)] = c[3];
            }
    }
}

// ---------------- generic GEMM --------------------------------------------------
// LNIN: LN fused into A reads; RESLN: LN fused into residual reads (res layout N==1024)
template<bool BIAS, bool RES, bool RELU, bool LNST, bool LNIN, bool RESLN>
__global__ __launch_bounds__(256, 2)
void hf_gemm(const float* __restrict__ A, const __half* __restrict__ Bp,
             const float* __restrict__ bias, const float* __restrict__ res,
             float* __restrict__ C, int N, int K,
             const float* __restrict__ lnw, const float* __restrict__ lnb)
{
    extern __shared__ __half smp[];
    const uint32_t sbase = (uint32_t)__cvta_generic_to_shared(smp);
    const int tid  = threadIdx.x;
    const int lane = tid & 31, wid = tid >> 5;
    const int g = lane >> 2, tig = lane & 3;
    const int quad = lane >> 3, rr = lane & 7;
    const int wm = wid >> 2, wn = wid & 3;
    const int m0 = blockIdx.y << 7, n0 = blockIdx.x << 7;
    const int aoff = ((rr + ((quad & 1) << 3)) * 40 + ((quad >> 1) << 3)) << 1;
    const int boff = ((rr + ((quad >> 1) << 3)) * 40 + ((quad & 1) << 3)) << 1;

    float acc[4][4][4];
#pragma unroll
    for (int mt = 0; mt < 4; mt++)
#pragma unroll
        for (int nt = 0; nt < 4; nt++)
#pragma unroll
            for (int c = 0; c < 4; c++) acc[mt][nt][c] = 0.f;

    gemm_mainloop<LNIN>(A, Bp, lnw, lnb, smp, sbase, acc, m0, n0, N, K, tid, wm, wn, aoff, boff);

    float ls = 0.f, lq = 0.f;
#pragma unroll
    for (int mt = 0; mt < 4; mt++) {
#pragma unroll
        for (int nt = 0; nt < 4; nt++) {
            const int m = m0 + (wm << 6) + (mt << 4) + g;
            const int n = n0 + (wn << 5) + (nt << 3) + (tig << 1);
            const float* c = acc[mt][nt];
            float2 v0 = make_float2(c[0], c[1]);
            float2 v1 = make_float2(c[2], c[3]);
            if (BIAS) {
                float2 bv = *(const float2*)(bias + n);
                v0.x += bv.x; v0.y += bv.y; v1.x += bv.x; v1.y += bv.y;
            }
            if (RES) {
                float2 r0 = *(const float2*)(res + (size_t)m * N + n);
                float2 r1 = *(const float2*)(res + (size_t)(m + 8) * N + n);
                if (RESLN) {
                    const int b = m >> 10;
                    const float mean = g_stats[b][0], inv = g_stats[b][1];
                    const size_t w0 = ((size_t)m * N + n) & 1048575;
                    const size_t w1 = ((size_t)(m + 8) * N + n) & 1048575;
                    float2 wv0 = *(const float2*)(lnw + w0);
                    float2 bv0 = *(const float2*)(lnb + w0);
                    float2 wv1 = *(const float2*)(lnw + w1);
                    float2 bv1 = *(const float2*)(lnb + w1);
                    r0.x = (r0.x - mean) * inv * wv0.x + bv0.x;
                    r0.y = (r0.y - mean) * inv * wv0.y + bv0.y;
                    r1.x = (r1.x - mean) * inv * wv1.x + bv1.x;
                    r1.y = (r1.y - mean) * inv * wv1.y + bv1.y;
                }
                v0.x += r0.x; v0.y += r0.y; v1.x += r1.x; v1.y += r1.y;
            }
            if (RELU) {
                v0.x = fmaxf(v0.x, 0.f); v0.y = fmaxf(v0.y, 0.f);
                v1.x = fmaxf(v1.x, 0.f); v1.y = fmaxf(v1.y, 0.f);
            }
            if (LNST) {
                ls += v0.x + v0.y + v1.x + v1.y;
                lq += v0.x * v0.x + v0.y * v0.y + v1.x * v1.x + v1.y * v1.y;
            }
            *(float2*)(C + (size_t)m * N + n) = v0;
            *(float2*)(C + (size_t)(m + 8) * N + n) = v1;
        }
    }

    if constexpr (LNST) {
        __syncthreads();
        double* sd = (double*)smp;
        double* sq = sd + 256;
        sd[tid] = (double)ls;
        sq[tid] = (double)lq;
        __syncthreads();
        for (int off = 128; off > 0; off >>= 1) {
            if (tid < off) { sd[tid] += sd[tid + off]; sq[tid] += sq[tid + off]; }
            __syncthreads();
        }
        if (tid == 0) {
            const int b = m0 >> 10;
            atomicAdd(&g_bstat[b][0], sd[0]);
            atomicAdd(&g_bstat[b][1], sq[0]);
        }
    }
}

// ---------------- tensor-core flash attention --------------------------------
__global__ __launch_bounds__(256)
void flash_mma_kernel(const float* __restrict__ Q, const float* __restrict__ KT,
                      const float* __restrict__ V, float* __restrict__ O2, int causal)
{
    extern __shared__ char fsm[];
    __half* Kh = (__half*)fsm;
    __half* Kl = Kh + 4608;
    __half* Vh = Kh + 9216;
    __half* Vl = Kh + 13824;
    float* smax = (float*)(fsm + 36864);
    float* ssum = smax + 128;
    float* sm_o = (float*)fsm;

    const int tid = threadIdx.x;
    const int lane = tid & 31, wid = tid >> 5;
    const int g = lane >> 2, tig = lane & 3;
    const int wm = wid >> 1, wn = wid & 1;
    const int s0 = blockIdx.x << 6;
    const int hb = blockIdx.y;
    const size_t base = (size_t)hb << 16;
    const int mrow = (wm << 4) + g;

#pragma unroll
    for (int it = 0; it < 4; it++) {
        const int flat = tid + (it << 8);
        const int r = flat >> 4, c4 = (flat & 15) << 2;
        float4 qv = *(const float4*)(Q + base + ((size_t)(s0 + r) << 6) + c4);
        float x[4] = {qv.x * 0.125f, qv.y * 0.125f, qv.z * 0.125f, qv.w * 0.125f};
        unsigned short u0[4], u1[4];
#pragma unroll
        for (int j = 0; j < 4; j++) {
            __half h0 = __float2half_rn(x[j]);
            float r1 = x[j] - __half2float(h0);
            u0[j] = __half_as_ushort(h0);
            u1[j] = __half_as_ushort(__float2half_rn(r1));
        }
        *(uint2*)&Kh[r * 72 + c4] = make_uint2(u0[0] | (u0[1] << 16), u0[2] | (u0[3] << 16));
        *(uint2*)&Kl[r * 72 + c4] = make_uint2(u1[0] | (u1[1] << 16), u1[2] | (u1[3] << 16));
    }
    __syncthreads();

    unsigned qh[4][4], ql[4][4];
#pragma unroll
    for (int kt = 0; kt < 4; kt++) {
        const int kb = kt << 4;
        qh[kt][0] = *(const unsigned*)&Kh[mrow * 72 + kb + (tig << 1)];
        qh[kt][1] = *(const unsigned*)&Kh[(mrow + 8) * 72 + kb + (tig << 1)];
        qh[kt][2] = *(const unsigned*)&Kh[mrow * 72 + kb + 8 + (tig << 1)];
        qh[kt][3] = *(const unsigned*)&Kh[(mrow + 8) * 72 + kb + 8 + (tig << 1)];
        ql[kt][0] = *(const unsigned*)&Kl[mrow * 72 + kb + (tig << 1)];
        ql[kt][1] = *(const unsigned*)&Kl[(mrow + 8) * 72 + kb + (tig << 1)];
        ql[kt][2] = *(const unsigned*)&Kl[mrow * 72 + kb + 8 + (tig << 1)];
        ql[kt][3] = *(const unsigned*)&Kl[(mrow + 8) * 72 + kb + 8 + (tig << 1)];
    }

    float o[8][4];
#pragma unroll
    for (int nt = 0; nt < 8; nt++)
#pragma unroll
        for (int c = 0; c < 4; c++) o[nt][c] = 0.f;
    float m0 = -INFINITY, m1 = -INFINITY, l0 = 0.f, l1 = 0.f;

    const int row0 = s0 + mrow, row1 = row0 + 8;
    const int ntiles = causal ? ((int)blockIdx.x + 1) : 16;

    for (int jt = 0; jt < ntiles; jt++) {
        const int t0 = jt << 6;
        __syncthreads();

#pragma unroll
        for (int it = 0; it < 4; it++) {
            const int flat = tid + (it << 8);
            const int r = flat >> 4, c4 = (flat & 15) << 2;
            float4 kv = *(const float4*)(KT + base + ((size_t)(t0 + r) << 6) + c4);
            float x[4] = {kv.x, kv.y, kv.z, kv.w};
            unsigned short u0[4], u1[4];
#pragma unroll
            for (int j = 0; j < 4; j++) {
                __half h0 = __float2half_rn(x[j]);
                float r1 = x[j] - __half2float(h0);
                u0[j] = __half_as_ushort(h0);
                u1[j] = __half_as_ushort(__float2half_rn(r1));
            }
            *(uint2*)&Kh[r * 72 + c4] = make_uint2(u0[0] | (u0[1] << 16), u0[2] | (u0[3] << 16));
            *(uint2*)&Kl[r * 72 + c4] = make_uint2(u1[0] | (u1[1] << 16), u1[2] | (u1[3] << 16));
        }
#pragma unroll
        for (int it = 0; it < 4; it++) {
            const int flat = tid + (it << 8);
            const int tr = flat >> 4, dv4 = (flat & 15) << 2;
            float4 vv = *(const float4*)(V + base + ((size_t)(t0 + tr) << 6) + dv4);
            float x[4] = {vv.x, vv.y, vv.z, vv.w};
#pragma unroll
            for (int j = 0; j < 4; j++) {
                const int dv = dv4 + j;
                const int sw = ((dv >> 2) & 7) << 3;
                const int idx = dv * 72 + (tr ^ sw);
                __half h0 = __float2half_rn(x[j]);
                float r1 = x[j] - __half2float(h0);
                Vh[idx] = h0;
                Vl[idx] = __float2half_rn(r1);
            }
        }
        __syncthreads();

        float sc[4][4];
#pragma unroll
        for (int nt = 0; nt < 4; nt++)
#pragma unroll
            for (int c = 0; c < 4; c++) sc[nt][c] = 0.f;
#pragma unroll
        for (int kt = 0; kt < 4; kt++) {
            const int kb = kt << 4;
#pragma unroll
            for (int nt = 0; nt < 4; nt++) {
                const int nr = (wn << 5) + (nt << 3) + g;
                unsigned b[2];
                b[0] = *(const unsigned*)&Kh[nr * 72 + kb + (tig << 1)];
                b[1] = *(const unsigned*)&Kh[nr * 72 + kb + 8 + (tig << 1)];
                mma_f16(sc[nt], qh[kt], b);
                mma_f16(sc[nt], ql[kt], b);
            }
        }
#pragma unroll
        for (int kt = 0; kt < 4; kt++) {
            const int kb = kt << 4;
#pragma unroll
            for (int nt = 0; nt < 4; nt++) {
                const int nr = (wn << 5) + (nt << 3) + g;
                unsigned b[2];
                b[0] = *(const unsigned*)&Kl[nr * 72 + kb + (tig << 1)];
                b[1] = *(const unsigned*)&Kl[nr * 72 + kb + 8 + (tig << 1)];
                mma_f16(sc[nt], qh[kt], b);
            }
        }

        float mx0 = -INFINITY, mx1 = -INFINITY;
#pragma unroll
        for (int nt = 0; nt < 4; nt++) {
            const int col = t0 + (wn << 5) + (nt << 3) + (tig << 1);
            if (causal) {
                if (col > row0)     sc[nt][0] = -INFINITY;
                if (col + 1 > row0) sc[nt][1] = -INFINITY;
                if (col > row1)     sc[nt][2] = -INFINITY;
                if (col + 1 > row1) sc[nt][3] = -INFINITY;
            }
            mx0 = fmaxf(mx0, fmaxf(sc[nt][0], sc[nt][1]));
            mx1 = fmaxf(mx1, fmaxf(sc[nt][2], sc[nt][3]));
        }
        mx0 = fmaxf(mx0, __shfl_xor_sync(0xffffffffu, mx0, 1));
        mx0 = fmaxf(mx0, __shfl_xor_sync(0xffffffffu, mx0, 2));
        mx1 = fmaxf(mx1, __shfl_xor_sync(0xffffffffu, mx1, 1));
        mx1 = fmaxf(mx1, __shfl_xor_sync(0xffffffffu, mx1, 2));
        smax[(wn << 6) + mrow] = mx0;
        smax[(wn << 6) + mrow + 8] = mx1;
        __syncthreads();

        const float mn0 = fmaxf(m0, fmaxf(smax[mrow], smax[64 + mrow]));
        const float mn1 = fmaxf(m1, fmaxf(smax[mrow + 8], smax[64 + mrow + 8]));
        const float cr0 = __expf(m0 - mn0);
        const float cr1 = __expf(m1 - mn1);
        m0 = mn0; m1 = mn1;
#pragma unroll
        for (int nt = 0; nt < 8; nt++) {
            o[nt][0] *= cr0; o[nt][1] *= cr0;
            o[nt][2] *= cr1; o[nt][3] *= cr1;
        }
        float p[4][4];
        float rs0 = 0.f, rs1 = 0.f;
#pragma unroll
        for (int nt = 0; nt < 4; nt++) {
            p[nt][0] = __expf(sc[nt][0] - mn0);
            p[nt][1] = __expf(sc[nt][1] - mn0);
            p[nt][2] = __expf(sc[nt][2] - mn1);
            p[nt][3] = __expf(sc[nt][3] - mn1);
            rs0 += p[nt][0] + p[nt][1];
            rs1 += p[nt][2] + p[nt][3];
        }
        rs0 += __shfl_xor_sync(0xffffffffu, rs0, 1);
        rs0 += __shfl_xor_sync(0xffffffffu, rs0, 2);
        rs1 += __shfl_xor_sync(0xffffffffu, rs1, 1);
        rs1 += __shfl_xor_sync(0xffffffffu, rs1, 2);
        ssum[(wn << 6) + mrow] = rs0;
        ssum[(wn << 6) + mrow + 8] = rs1;
        __syncthreads();
        l0 = l0 * cr0 + ssum[mrow] + ssum[64 + mrow];
        l1 = l1 * cr1 + ssum[mrow + 8] + ssum[64 + mrow + 8];

        unsigned ah[2][4], al[2][4];
#pragma unroll
        for (int kc = 0; kc < 2; kc++) {
            const int ta = kc << 1, tb = ta + 1;
            float h00 = __half2float(__float2half_rn(p[ta][0]));
            float h01 = __half2float(__float2half_rn(p[ta][1]));
            float h02 = __half2float(__float2half_rn(p[ta][2]));
            float h03 = __half2float(__float2half_rn(p[ta][3]));
            float h10 = __half2float(__float2half_rn(p[tb][0]));
            float h11 = __half2float(__float2half_rn(p[tb][1]));
            float h12 = __half2float(__float2half_rn(p[tb][2]));
            float h13 = __half2float(__float2half_rn(p[tb][3]));
            ah[kc][0] = pack_h2(h00, h01);
            ah[kc][1] = pack_h2(h02, h03);
            ah[kc][2] = pack_h2(h10, h11);
            ah[kc][3] = pack_h2(h12, h13);
            al[kc][0] = pack_h2(p[ta][0] - h00, p[ta][1] - h01);
            al[kc][1] = pack_h2(p[ta][2] - h02, p[ta][3] - h03);
            al[kc][2] = pack_h2(p[tb][0] - h10, p[tb][1] - h11);
            al[kc][3] = pack_h2(p[tb][2] - h12, p[tb][3] - h13);
        }

#pragma unroll
        for (int nt = 0; nt < 8; nt++) {
            const int dv = (nt << 3) + g;
            const int sw = ((dv >> 2) & 7) << 3;
            const int rb = dv * 72;
#pragma unroll
            for (int kc = 0; kc < 2; kc++) {
                const int kg = (wn << 5) + (kc << 4);
                unsigned vb[2], wb[2];
                vb[0] = *(const unsigned*)&Vh[rb + ((kg ^ sw) + (tig << 1))];
                vb[1] = *(const unsigned*)&Vh[rb + (((kg + 8) ^ sw) + (tig << 1))];
                mma_f16(o[nt], ah[kc], vb);
                mma_f16(o[nt], al[kc], vb);
                wb[0] = *(const unsigned*)&Vl[rb + ((kg ^ sw) + (tig << 1))];
                wb[1] = *(const unsigned*)&Vl[rb + (((kg + 8) ^ sw) + (tig << 1))];
                mma_f16(o[nt], ah[kc], wb);
            }
        }
    }

    const float il0 = 1.f / l0, il1 = 1.f / l1;
#pragma unroll
    for (int nt = 0; nt < 8; nt++) {
        o[nt][0] *= il0; o[nt][1] *= il0;
        o[nt][2] *= il1; o[nt][3] *= il1;
    }
    __syncthreads();
    float* po = sm_o + wn * 4608;
#pragma unroll
    for (int nt = 0; nt < 8; nt++) {
        const int dv = (nt << 3) + (tig << 1);
        *(float2*)&po[mrow * 72 + dv]       = make_float2(o[nt][0], o[nt][1]);
        *(float2*)&po[(mrow + 8) * 72 + dv] = make_float2(o[nt][2], o[nt][3]);
    }
    __syncthreads();
    if (wn == 0) {
        const int h = hb >> 2, b = hb & 3;
        const int r = lane >> 1;
        const int dvh = (lane & 1) << 5;
        const int row = (wm << 4) + r;
        const int s = s0 + row;
        const size_t orow = ((size_t)((h >> 2) * 1024 + (h & 3) * 256 + b * 64 + (s >> 4)) << 10)
                          + ((s & 15) << 6);
#pragma unroll
        for (int i = 0; i < 8; i++) {
            const int dv = dvh + (i << 2);
            float4 a = *(const float4*)&sm_o[row * 72 + dv];
            float4 bb = *(const float4*)&sm_o[4608 + row * 72 + dv];
            float4 vv = make_float4(a.x + bb.x, a.y + bb.y, a.z + bb.z, a.w + bb.w);
            *(float4*)(O2 + orow + dv) = vv;
        }
    }
}

// ---------------- LN finalize + apply ----------------------------------------
__global__ void ln_final_kernel()
{
    const int b = threadIdx.x;
    if (b < 4) {
        const double inv_n = 1.0 / 1048576.0;
        const double mean = g_bstat[b][0] * inv_n;
        const double var = g_bstat[b][1] * inv_n - mean * mean;
        g_stats[b][0] = (float)mean;
        g_stats[b][1] = (float)(1.0 / sqrt(var + 1e-5));
        g_bstat[b][0] = 0.0;
        g_bstat[b][1] = 0.0;
    }
}

__global__ void ln_apply_kernel(const float* __restrict__ X, const float* __restrict__ w,
                                const float* __restrict__ bb, float* __restrict__ Y)
{
    const size_t i = ((size_t)blockIdx.x * 256 + threadIdx.x) << 2;
    const int b = (int)(i >> 20);
    const float mean = g_stats[b][0], inv = g_stats[b][1];
    const size_t wi = i & 1048575;
    float4 x = *(const float4*)(X + i);
    float4 wv = *(const float4*)(w + wi);
    float4 bv = *(const float4*)(bb + wi);
    float4 y;
    y.x = (x.x - mean) * inv * wv.x + bv.x;
    y.y = (x.y - mean) * inv * wv.y + bv.y;
    y.z = (x.z - mean) * inv * wv.z + bv.z;
    y.w = (x.w - mean) * inv * wv.w + bv.w;
    *(float4*)(Y + i) = y;
}

// ---------------- driver -----------------------------------------------------
extern "C" void kernel_launch(void* const* d_in, const int* in_sizes, int n_in,
                              void* d_out, int out_size)
{
    const float* inputRes = (const float*)d_in[0];
    const float* outEnc   = (const float*)d_in[1];
    const float* ln1w = (const float*)d_in[10];
    const float* ln1b = (const float*)d_in[11];
    const float* ln2w = (const float*)d_in[12];
    const float* ln2b = (const float*)d_in[13];
    const float* ln3w = (const float*)d_in[14];
    const float* ln3b = (const float*)d_in[15];
    const float* W1 = (const float*)d_in[16];
    const float* b1 = (const float*)d_in[17];
    const float* W2 = (const float*)d_in[18];
    const float* b2 = (const float*)d_in[19];
    float* out = (float*)d_out;

    float *q, *kT, *v, *o2, *t1, *fc1;
    __half* ws;
    cudaGetSymbolAddress((void**)&q,   g_q);
    cudaGetSymbolAddress((void**)&kT,  g_kT);
    cudaGetSymbolAddress((void**)&v,   g_v);
    cudaGetSymbolAddress((void**)&o2,  g_o2);
    cudaGetSymbolAddress((void**)&t1,  g_t1);
    cudaGetSymbolAddress((void**)&fc1, g_fc1);
    cudaGetSymbolAddress((void**)&ws,  g_ws);

    const int FSM = 37888;
    cudaFuncSetAttribute(flash_mma_kernel, cudaFuncAttributeMaxDynamicSharedMemorySize, FSM);

    const int SMH = 81920;
    cudaFuncSetAttribute(hf_gemm_proj<false>, cudaFuncAttributeMaxDynamicSharedMemorySize, SMH);
    cudaFuncSetAttribute(hf_gemm_proj<true>, cudaFuncAttributeMaxDynamicSharedMemorySize, SMH);
    cudaFuncSetAttribute(hf_gemm<false, true, false, true, false, false>, cudaFuncAttributeMaxDynamicSharedMemorySize, SMH);
    cudaFuncSetAttribute(hf_gemm<true, false, true, false, true, false>, cudaFuncAttributeMaxDynamicSharedMemorySize, SMH);
    cudaFuncSetAttribute(hf_gemm<true, true, false, true, false, true>, cudaFuncAttributeMaxDynamicSharedMemorySize, SMH);

    dim3 blk(256);

    // ---- pre-split weights + clear LN accumulators ----
    W8Pack pk;
    pk.w[0] = (const float*)d_in[2]; pk.w[1] = (const float*)d_in[3];
    pk.w[2] = (const float*)d_in[4]; pk.w[3] = (const float*)d_in[5];
    pk.w[4] = (const float*)d_in[6]; pk.w[5] = (const float*)d_in[7];
    pk.w[6] = (const float*)d_in[8]; pk.w[7] = (const float*)d_in[9];
    clear_stats_kernel<<<1, 32>>>();
    wsplit8_kernel<<<dim3(16, 16, 8), blk>>>(pk, ws);
    wsplit_kernel<<<dim3(32, 16), blk>>>(W1, ws + OFF_W1, 2048, 1024);
    wsplit_kernel<<<dim3(16, 32), blk>>>(W2, ws + OFF_W2, 1024, 2048);

    dim3 g1024(8, 32), g2048(16, 32);

    // ---- MHA1 (self, causal): fused QKV projection ----
    ProjPack p1;
    p1.j[0] = {ws + OFF_WQ1, q, 0};
    p1.j[1] = {ws + OFF_WK1, kT, 1};
    p1.j[2] = {ws + OFF_WV1, v, 0};
    hf_gemm_proj<false><<<dim3(8, 32, 3), blk, SMH>>>(outEnc, p1, 1024, nullptr, nullptr);
    flash_mma_kernel<<<dim3(16, 64), blk, FSM>>>(q, kT, v, o2, 1);
    hf_gemm<false, true, false, true, false, false><<<g1024, blk, SMH>>>(
        o2, ws + OFF_WO1, nullptr, outEnc, t1, 1024, 1024, nullptr, nullptr);
    ln_final_kernel<<<1, 32>>>();
    // (LN1 apply fused into Q2 projection's A-load)

    // ---- MHA2 (cross): KV from inputRes, Q from LN1(t1) ----
    ProjPack p2;
    p2.j[0] = {ws + OFF_WK2, kT, 1};
    p2.j[1] = {ws + OFF_WV2, v, 0};
    p2.j[2] = {nullptr, nullptr, 0};
    hf_gemm_proj<false><<<dim3(8, 32, 2), blk, SMH>>>(inputRes, p2, 1024, nullptr, nullptr);
    ProjPack p3;
    p3.j[0] = {ws + OFF_WQ2, q, 0};
    p3.j[1] = {nullptr, nullptr, 0};
    p3.j[2] = {nullptr, nullptr, 0};
    hf_gemm_proj<true><<<dim3(8, 32, 1), blk, SMH>>>(t1, p3, 1024, ln1w, ln1b);
    flash_mma_kernel<<<dim3(16, 64), blk, FSM>>>(q, kT, v, o2, 0);
    hf_gemm<false, true, false, true, false, false><<<g1024, blk, SMH>>>(
        o2, ws + OFF_WO2, nullptr, outEnc, t1, 1024, 1024, nullptr, nullptr);
    ln_final_kernel<<<1, 32>>>();
    // (LN2 apply fused into FFN1 A-load and FFN2 residual)

    // ---- FFN ----
    hf_gemm<true, false, true, false, true, false><<<g2048, blk, SMH>>>(
        t1, ws + OFF_W1, b1, nullptr, fc1, 2048, 1024, ln2w, ln2b);
    hf_gemm<true, true, false, true, false, true><<<g1024, blk, SMH>>>(
        fc1, ws + OFF_W2, b2, t1, t1, 1024, 2048, ln2w, ln2b);
    ln_final_kernel<<<1, 32>>>();
    ln_apply_kernel<<<4096, blk>>>(t1, ln3w, ln3b, out);
}

// round 16
// speedup vs baseline: 1.0256x; 1.0256x over previous
#include <cuda_runtime.h>
#include <cuda_fp16.h>
#include <math.h>
#include <stdint.h>

#define N_ELEM 4194304  // 4*1024*1024

// ---------------- scratch (device globals) ----------------------------------
__device__ float  g_q [N_ELEM];
__device__ float  g_kT[N_ELEM];
__device__ float  g_v [N_ELEM];
__device__ float  g_o2[N_ELEM];
__device__ float  g_t1[N_ELEM];
__device__ float  g_n1[N_ELEM];
__device__ float  g_n2[N_ELEM];
__device__ float  g_fc1[4096 * 2048];
__device__ double g_bstat[4][2];   // {sum, sumsq} per batch
__device__ float  g_stats[4][2];   // {mean, invstd}
__device__ __align__(16) __half g_ws[25165824];  // weight planes [2][N][K]

#define OFF_WQ1 0
#define OFF_WK1 2097152
#define OFF_WV1 4194304
#define OFF_WO1 6291456
#define OFF_WQ2 8388608
#define OFF_WK2 10485760
#define OFF_WV2 12582912
#define OFF_WO2 14680064
#define OFF_W1  16777216
#define OFF_W2  20971520

// ---------------- PTX helpers -------------------------------------------------
__device__ __forceinline__ void mma_f16(float* c, const unsigned* a, const unsigned* b) {
    asm volatile(
        "mma.sync.aligned.m16n8k16.row.col.f32.f16.f16.f32 "
        "{%0,%1,%2,%3}, {%4,%5,%6,%7}, {%8,%9}, {%0,%1,%2,%3};\n"
        : "+f"(c[0]), "+f"(c[1]), "+f"(c[2]), "+f"(c[3])
        : "r"(a[0]), "r"(a[1]), "r"(a[2]), "r"(a[3]), "r"(b[0]), "r"(b[1]));
}
__device__ __forceinline__ unsigned pack_h2(float a, float b) {
    __half2 h = __floats2half2_rn(a, b);
    return *(unsigned*)&h;
}
__device__ __forceinline__ void ldsm4(unsigned* r, uint32_t a) {
    asm volatile("ldmatrix.sync.aligned.m8n8.x4.shared.b16 {%0,%1,%2,%3}, [%4];"
        : "=r"(r[0]), "=r"(r[1]), "=r"(r[2]), "=r"(r[3]) : "r"(a));
}
__device__ __forceinline__ void cp16(uint32_t dst, const void* src) {
    asm volatile("cp.async.cg.shared.global [%0], [%1], 16;" :: "r"(dst), "l"(src));
}
#define CP_COMMIT() asm volatile("cp.async.commit_group;" ::: "memory")
#define CP_WAIT0()  asm volatile("cp.async.wait_group 0;" ::: "memory")

// ---------------- weight transpose + 2-way fp16 split ------------------------
struct W8Pack { const float* w[8]; };

__device__ __forceinline__ void wsplit_body(const float* __restrict__ W,
                                            __half* __restrict__ out,
                                            int N, int K, bool proj,
                                            int n0, int k0, int tid)
{
    __shared__ float t[64][65];
#pragma unroll
    for (int r = 0; r < 4; r++) {
        const int flat = tid + (r << 8);
        const int kr = flat >> 4, nc = (flat & 15) << 2;
        const float* src;
        if (proj) src = W + ((size_t)((n0 + nc) >> 6) << 16) + ((size_t)(k0 + kr) << 6) + ((n0 + nc) & 63);
        else      src = W + (size_t)(k0 + kr) * N + n0 + nc;
        float4 v = *(const float4*)src;
        t[kr][nc] = v.x; t[kr][nc + 1] = v.y; t[kr][nc + 2] = v.z; t[kr][nc + 3] = v.w;
    }
    __syncthreads();
    const size_t ps = (size_t)N * K;
#pragma unroll
    for (int r = 0; r < 4; r++) {
        const int flat = tid + (r << 8);
        const int nr = flat >> 4, kc = (flat & 15) << 2;
        unsigned short u0[4], u1[4];
#pragma unroll
        for (int j = 0; j < 4; j++) {
            float x = t[kc + j][nr];
            __half h0 = __float2half_rn(x);
            float r1 = x - __half2float(h0);
            u0[j] = __half_as_ushort(h0);
            u1[j] = __half_as_ushort(__float2half_rn(r1));
        }
        const size_t dst = (size_t)(n0 + nr) * K + k0 + kc;
        *(uint2*)(out + dst)      = make_uint2(u0[0] | (u0[1] << 16), u0[2] | (u0[3] << 16));
        *(uint2*)(out + ps + dst) = make_uint2(u1[0] | (u1[1] << 16), u1[2] | (u1[3] << 16));
    }
}

__global__ __launch_bounds__(256)
void wsplit8_kernel(W8Pack pk, __half* __restrict__ out)
{
    const int z = blockIdx.z;
    const bool proj = (z & 3) != 3;
    wsplit_body(pk.w[z], out + (size_t)z * 2097152, 1024, 1024, proj,
                blockIdx.x << 6, blockIdx.y << 6, threadIdx.x);
}

__global__ __launch_bounds__(256)
void wsplit_kernel(const float* __restrict__ W, __half* __restrict__ out, int N, int K)
{
    wsplit_body(W, out, N, K, false, blockIdx.x << 6, blockIdx.y << 6, threadIdx.x);
}

__global__ void clear_stats_kernel()
{
    if (threadIdx.x < 8) ((double*)g_bstat)[threadIdx.x] = 0.0;
}

// ---------------- GEMM core (shared mainloop) ---------------------------------
struct ProjJob { const __half* Bp; float* C; int mode; };  // mode 0 std, 1 kT
struct ProjPack { ProjJob j[3]; };

__device__ __forceinline__ void gemm_mainloop(
    const float* __restrict__ A, const __half* __restrict__ Bp,
    __half* smp, uint32_t sbase, float acc[4][4][4],
    int m0, int n0, int N, int K, int tid, int wm, int wn, int aoff, int boff)
{
    const size_t bstride = (size_t)N * K;
    const int nstage = K >> 5;

    // ---- prologue: B(0) via cp.async, A(0) direct ----
#pragma unroll
    for (int p = 0; p < 2; p++)
#pragma unroll
        for (int r = 0; r < 2; r++) {
            const int flat = tid + (r << 8);
            const int row = flat >> 2, cs = (flat & 3) << 3;
            cp16(sbase + 20480 + p * 10240 + ((row * 40 + cs) << 1),
                 Bp + (size_t)p * bstride + (size_t)(n0 + row) * K + cs);
        }
    CP_COMMIT();
#pragma unroll
    for (int r = 0; r < 4; r++) {
        const int flat = tid + (r << 8);
        const int row = flat >> 3, c4 = (flat & 7) << 2;
        float4 av = *(const float4*)(A + (size_t)(m0 + row) * K + c4);
        float x[4] = {av.x, av.y, av.z, av.w};
        unsigned short u0[4], u1[4];
#pragma unroll
        for (int j = 0; j < 4; j++) {
            __half h0 = __float2half_rn(x[j]);
            float r1 = x[j] - __half2float(h0);
            u0[j] = __half_as_ushort(h0);
            u1[j] = __half_as_ushort(__float2half_rn(r1));
        }
        const int off = row * 40 + c4;
        *(uint2*)(smp + off)        = make_uint2(u0[0] | (u0[1] << 16), u0[2] | (u0[3] << 16));
        *(uint2*)(smp + 5120 + off) = make_uint2(u1[0] | (u1[1] << 16), u1[2] | (u1[3] << 16));
    }

    for (int s = 0; s < nstage; s++) {
        const uint32_t stg = (uint32_t)(s & 1) * 40960u;
        CP_WAIT0();
        __syncthreads();

        float4 pa2[4];
        const int kn = (s + 1) << 5;
        const bool more = kn < K;
        if (more) {
            const uint32_t nst = (uint32_t)((s + 1) & 1) * 40960u;
#pragma unroll
            for (int p = 0; p < 2; p++)
#pragma unroll
                for (int r = 0; r < 2; r++) {
                    const int flat = tid + (r << 8);
                    const int row = flat >> 2, cs = (flat & 3) << 3;
                    cp16(sbase + nst + 20480 + p * 10240 + ((row * 40 + cs) << 1),
                         Bp + (size_t)p * bstride + (size_t)(n0 + row) * K + kn + cs);
                }
            CP_COMMIT();
#pragma unroll
            for (int r = 0; r < 4; r++) {
                const int flat = tid + (r << 8);
                const int row = flat >> 3, c4 = (flat & 7) << 2;
                pa2[r] = *(const float4*)(A + (size_t)(m0 + row) * K + kn + c4);
            }
        }

        const uint32_t Ab = sbase + stg;
        const uint32_t Bb = sbase + stg + 20480;
#pragma unroll
        for (int kt = 0; kt < 2; kt++) {
            const int kbB = kt << 5;
            unsigned a0[4][4], b0[4][2], bx[4][2], a1[4][4];
#pragma unroll
            for (int mt = 0; mt < 4; mt++)
                ldsm4(a0[mt], Ab + ((((wm << 6) + (mt << 4)) * 40) << 1) + kbB + aoff);
#pragma unroll
            for (int nh = 0; nh < 2; nh++) {
                unsigned t4[4];
                ldsm4(t4, Bb + ((((wn << 5) + (nh << 4)) * 40) << 1) + kbB + boff);
                b0[2 * nh][0] = t4[0]; b0[2 * nh][1] = t4[1];
                b0[2 * nh + 1][0] = t4[2]; b0[2 * nh + 1][1] = t4[3];
            }
#pragma unroll
            for (int mt = 0; mt < 4; mt++)
#pragma unroll
                for (int nt = 0; nt < 4; nt++)
                    mma_f16(acc[mt][nt], a0[mt], b0[nt]);   // Ah*Bh
#pragma unroll
            for (int nh = 0; nh < 2; nh++) {
                unsigned t4[4];
                ldsm4(t4, Bb + 10240 + ((((wn << 5) + (nh << 4)) * 40) << 1) + kbB + boff);
                bx[2 * nh][0] = t4[0]; bx[2 * nh][1] = t4[1];
                bx[2 * nh + 1][0] = t4[2]; bx[2 * nh + 1][1] = t4[3];
            }
#pragma unroll
            for (int mt = 0; mt < 4; mt++)
#pragma unroll
                for (int nt = 0; nt < 4; nt++)
                    mma_f16(acc[mt][nt], a0[mt], bx[nt]);   // Ah*Bl
#pragma unroll
            for (int mt = 0; mt < 4; mt++)
                ldsm4(a1[mt], Ab + 10240 + ((((wm << 6) + (mt << 4)) * 40) << 1) + kbB + aoff);
#pragma unroll
            for (int mt = 0; mt < 4; mt++)
#pragma unroll
                for (int nt = 0; nt < 4; nt++)
                    mma_f16(acc[mt][nt], a1[mt], b0[nt]);   // Al*Bh
        }

        if (more) {
            __half* An = smp + ((s + 1) & 1) * 20480;
#pragma unroll
            for (int r = 0; r < 4; r++) {
                const int flat = tid + (r << 8);
                const int row = flat >> 3, c4 = (flat & 7) << 2;
                float x[4] = {pa2[r].x, pa2[r].y, pa2[r].z, pa2[r].w};
                unsigned short u0[4], u1[4];
#pragma unroll
                for (int j = 0; j < 4; j++) {
                    __half h0 = __float2half_rn(x[j]);
                    float r1 = x[j] - __half2float(h0);
                    u0[j] = __half_as_ushort(h0);
                    u1[j] = __half_as_ushort(__float2half_rn(r1));
                }
                const int off = row * 40 + c4;
                *(uint2*)(An + off)        = make_uint2(u0[0] | (u0[1] << 16), u0[2] | (u0[3] << 16));
                *(uint2*)(An + 5120 + off) = make_uint2(u1[0] | (u1[1] << 16), u1[2] | (u1[3] << 16));
            }
        }
    }
}

// ---------------- fused multi-projection GEMM (z selects weight/output) ------
__global__ __launch_bounds__(256, 2)
void hf_gemm_proj(const float* __restrict__ A, ProjPack pk, int K)
{
    extern __shared__ __half smp[];
    const uint32_t sbase = (uint32_t)__cvta_generic_to_shared(smp);
    const int tid  = threadIdx.x;
    const int lane = tid & 31, wid = tid >> 5;
    const int g = lane >> 2, tig = lane & 3;
    const int quad = lane >> 3, rr = lane & 7;
    const int wm = wid >> 2, wn = wid & 3;
    const int m0 = blockIdx.y << 7, n0 = blockIdx.x << 7;
    const int aoff = ((rr + ((quad & 1) << 3)) * 40 + ((quad >> 1) << 3)) << 1;
    const int boff = ((rr + ((quad >> 1) << 3)) * 40 + ((quad & 1) << 3)) << 1;
    const ProjJob job = pk.j[blockIdx.z];

    float acc[4][4][4];
#pragma unroll
    for (int mt = 0; mt < 4; mt++)
#pragma unroll
        for (int nt = 0; nt < 4; nt++)
#pragma unroll
            for (int c = 0; c < 4; c++) acc[mt][nt][c] = 0.f;

    gemm_mainloop(A, job.Bp, smp, sbase, acc, m0, n0, 1024, K, tid, wm, wn, aoff, boff);

    float* C = job.C;
    if (job.mode == 0) {
#pragma unroll
        for (int mt = 0; mt < 4; mt++)
#pragma unroll
            for (int nt = 0; nt < 4; nt++) {
                const int m = m0 + (wm << 6) + (mt << 4) + g;
                const int n = n0 + (wn << 5) + (nt << 3) + (tig << 1);
                const float* c = acc[mt][nt];
                const int b = m >> 10, s = m & 1023;
                const int h = n >> 6, d = n & 63;
                const size_t hb = (size_t)(h * 4 + b);
                *(float2*)(C + (((hb << 10) + s) << 6) + d) = make_float2(c[0], c[1]);
                *(float2*)(C + (((hb << 10) + s + 8) << 6) + d) = make_float2(c[2], c[3]);
            }
    } else {
#pragma unroll
        for (int mt = 0; mt < 4; mt++)
#pragma unroll
            for (int nt = 0; nt < 4; nt++) {
                const int m = m0 + (wm << 6) + (mt << 4) + g;
                const int n = n0 + (wn << 5) + (nt << 3) + (tig << 1);
                const float* c = acc[mt][nt];
                const int b = m >> 10, s = m & 1023;
                const int h = n >> 6, d = n & 63;
                const size_t hb = (size_t)(h * 4 + b);
                const int t0a = ((s & 15) << 6) | d;
                const int t0b = (((s + 8) & 15) << 6) | d;
                C[((hb << 10) + t0a)     * 64 + (s >> 4)]       = c[0];
                C[((hb << 10) + t0a + 1) * 64 + (s >> 4)]       = c[1];
                C[((hb << 10) + t0b)     * 64 + ((s + 8) >> 4)] = c[2];
                C[((hb << 10) + t0b + 1) * 64 + ((s + 8) >> 4)] = c[3];
            }
    }
}

// ---------------- generic GEMM (row-major out, +bias/res/relu, +LN stats) ----
template<bool BIAS, bool RES, bool RELU, bool LNST>
__global__ __launch_bounds__(256, 2)
void hf_gemm(const float* __restrict__ A, const __half* __restrict__ Bp,
             const float* __restrict__ bias, const float* __restrict__ res,
             float* __restrict__ C, int N, int K)
{
    extern __shared__ __half smp[];
    const uint32_t sbase = (uint32_t)__cvta_generic_to_shared(smp);
    const int tid  = threadIdx.x;
    const int lane = tid & 31, wid = tid >> 5;
    const int g = lane >> 2, tig = lane & 3;
    const int quad = lane >> 3, rr = lane & 7;
    const int wm = wid >> 2, wn = wid & 3;
    const int m0 = blockIdx.y << 7, n0 = blockIdx.x << 7;
    const int aoff = ((rr + ((quad & 1) << 3)) * 40 + ((quad >> 1) << 3)) << 1;
    const int boff = ((rr + ((quad >> 1) << 3)) * 40 + ((quad & 1) << 3)) << 1;

    float acc[4][4][4];
#pragma unroll
    for (int mt = 0; mt < 4; mt++)
#pragma unroll
        for (int nt = 0; nt < 4; nt++)
#pragma unroll
            for (int c = 0; c < 4; c++) acc[mt][nt][c] = 0.f;

    gemm_mainloop(A, Bp, smp, sbase, acc, m0, n0, N, K, tid, wm, wn, aoff, boff);

    float ls = 0.f, lq = 0.f;
#pragma unroll
    for (int mt = 0; mt < 4; mt++) {
#pragma unroll
        for (int nt = 0; nt < 4; nt++) {
            const int m = m0 + (wm << 6) + (mt << 4) + g;
            const int n = n0 + (wn << 5) + (nt << 3) + (tig << 1);
            const float* c = acc[mt][nt];
            float2 v0 = make_float2(c[0], c[1]);
            float2 v1 = make_float2(c[2], c[3]);
            if (BIAS) {
                float2 bv = *(const float2*)(bias + n);
                v0.x += bv.x; v0.y += bv.y; v1.x += bv.x; v1.y += bv.y;
            }
            if (RES) {
                float2 r0 = *(const float2*)(res + (size_t)m * N + n);
                float2 r1 = *(const float2*)(res + (size_t)(m + 8) * N + n);
                v0.x += r0.x; v0.y += r0.y; v1.x += r1.x; v1.y += r1.y;
            }
            if (RELU) {
                v0.x = fmaxf(v0.x, 0.f); v0.y = fmaxf(v0.y, 0.f);
                v1.x = fmaxf(v1.x, 0.f); v1.y = fmaxf(v1.y, 0.f);
            }
            if (LNST) {
                ls += v0.x + v0.y + v1.x + v1.y;
                lq += v0.x * v0.x + v0.y * v0.y + v1.x * v1.x + v1.y * v1.y;
            }
            *(float2*)(C + (size_t)m * N + n) = v0;
            *(float2*)(C + (size_t)(m + 8) * N + n) = v1;
        }
    }

    if constexpr (LNST) {
        __syncthreads();
        double* sd = (double*)smp;
        double* sq = sd + 256;
        sd[tid] = (double)ls;
        sq[tid] = (double)lq;
        __syncthreads();
        for (int off = 128; off > 0; off >>= 1) {
            if (tid < off) { sd[tid] += sd[tid + off]; sq[tid] += sq[tid + off]; }
            __syncthreads();
        }
        if (tid == 0) {
            const int b = m0 >> 10;
            atomicAdd(&g_bstat[b][0], sd[0]);
            atomicAdd(&g_bstat[b][1], sq[0]);
        }
    }
}

// ---------------- tensor-core flash attention --------------------------------
__global__ __launch_bounds__(256)
void flash_mma_kernel(const float* __restrict__ Q, const float* __restrict__ KT,
                      const float* __restrict__ V, float* __restrict__ O2, int causal)
{
    extern __shared__ char fsm[];
    __half* Kh = (__half*)fsm;
    __half* Kl = Kh + 4608;
    __half* Vh = Kh + 9216;
    __half* Vl = Kh + 13824;
    float* smax = (float*)(fsm + 36864);
    float* ssum = smax + 128;
    float* sm_o = (float*)fsm;

    const int tid = threadIdx.x;
    const int lane = tid & 31, wid = tid >> 5;
    const int g = lane >> 2, tig = lane & 3;
    const int wm = wid >> 1, wn = wid & 1;
    const int s0 = blockIdx.x << 6;
    const int hb = blockIdx.y;
    const size_t base = (size_t)hb << 16;
    const int mrow = (wm << 4) + g;

#pragma unroll
    for (int it = 0; it < 4; it++) {
        const int flat = tid + (it << 8);
        const int r = flat >> 4, c4 = (flat & 15) << 2;
        float4 qv = *(const float4*)(Q + base + ((size_t)(s0 + r) << 6) + c4);
        float x[4] = {qv.x * 0.125f, qv.y * 0.125f, qv.z * 0.125f, qv.w * 0.125f};
        unsigned short u0[4], u1[4];
#pragma unroll
        for (int j = 0; j < 4; j++) {
            __half h0 = __float2half_rn(x[j]);
            float r1 = x[j] - __half2float(h0);
            u0[j] = __half_as_ushort(h0);
            u1[j] = __half_as_ushort(__float2half_rn(r1));
        }
        *(uint2*)&Kh[r * 72 + c4] = make_uint2(u0[0] | (u0[1] << 16), u0[2] | (u0[3] << 16));
        *(uint2*)&Kl[r * 72 + c4] = make_uint2(u1[0] | (u1[1] << 16), u1[2] | (u1[3] << 16));
    }
    __syncthreads();

    unsigned qh[4][4], ql[4][4];
#pragma unroll
    for (int kt = 0; kt < 4; kt++) {
        const int kb = kt << 4;
        qh[kt][0] = *(const unsigned*)&Kh[mrow * 72 + kb + (tig << 1)];
        qh[kt][1] = *(const unsigned*)&Kh[(mrow + 8) * 72 + kb + (tig << 1)];
        qh[kt][2] = *(const unsigned*)&Kh[mrow * 72 + kb + 8 + (tig << 1)];
        qh[kt][3] = *(const unsigned*)&Kh[(mrow + 8) * 72 + kb + 8 + (tig << 1)];
        ql[kt][0] = *(const unsigned*)&Kl[mrow * 72 + kb + (tig << 1)];
        ql[kt][1] = *(const unsigned*)&Kl[(mrow + 8) * 72 + kb + (tig << 1)];
        ql[kt][2] = *(const unsigned*)&Kl[mrow * 72 + kb + 8 + (tig << 1)];
        ql[kt][3] = *(const unsigned*)&Kl[(mrow + 8) * 72 + kb + 8 + (tig << 1)];
    }

    float o[8][4];
#pragma unroll
    for (int nt = 0; nt < 8; nt++)
#pragma unroll
        for (int c = 0; c < 4; c++) o[nt][c] = 0.f;
    float m0 = -INFINITY, m1 = -INFINITY, l0 = 0.f, l1 = 0.f;

    const int row0 = s0 + mrow, row1 = row0 + 8;
    const int ntiles = causal ? ((int)blockIdx.x + 1) : 16;

    for (int jt = 0; jt < ntiles; jt++) {
        const int t0 = jt << 6;
        __syncthreads();

#pragma unroll
        for (int it = 0; it < 4; it++) {
            const int flat = tid + (it << 8);
            const int r = flat >> 4, c4 = (flat & 15) << 2;
            float4 kv = *(const float4*)(KT + base + ((size_t)(t0 + r) << 6) + c4);
            float x[4] = {kv.x, kv.y, kv.z, kv.w};
            unsigned short u0[4], u1[4];
#pragma unroll
            for (int j = 0; j < 4; j++) {
                __half h0 = __float2half_rn(x[j]);
                float r1 = x[j] - __half2float(h0);
                u0[j] = __half_as_ushort(h0);
                u1[j] = __half_as_ushort(__float2half_rn(r1));
            }
            *(uint2*)&Kh[r * 72 + c4] = make_uint2(u0[0] | (u0[1] << 16), u0[2] | (u0[3] << 16));
            *(uint2*)&Kl[r * 72 + c4] = make_uint2(u1[0] | (u1[1] << 16), u1[2] | (u1[3] << 16));
        }
#pragma unroll
        for (int it = 0; it < 4; it++) {
            const int flat = tid + (it << 8);
            const int tr = flat >> 4, dv4 = (flat & 15) << 2;
            float4 vv = *(const float4*)(V + base + ((size_t)(t0 + tr) << 6) + dv4);
            float x[4] = {vv.x, vv.y, vv.z, vv.w};
#pragma unroll
            for (int j = 0; j < 4; j++) {
                const int dv = dv4 + j;
                const int sw = ((dv >> 2) & 7) << 3;
                const int idx = dv * 72 + (tr ^ sw);
                __half h0 = __float2half_rn(x[j]);
                float r1 = x[j] - __half2float(h0);
                Vh[idx] = h0;
                Vl[idx] = __float2half_rn(r1);
            }
        }
        __syncthreads();

        float sc[4][4];
#pragma unroll
        for (int nt = 0; nt < 4; nt++)
#pragma unroll
            for (int c = 0; c < 4; c++) sc[nt][c] = 0.f;
#pragma unroll
        for (int kt = 0; kt < 4; kt++) {
            const int kb = kt << 4;
#pragma unroll
            for (int nt = 0; nt < 4; nt++) {
                const int nr = (wn << 5) + (nt << 3) + g;
                unsigned b[2];
                b[0] = *(const unsigned*)&Kh[nr * 72 + kb + (tig << 1)];
                b[1] = *(const unsigned*)&Kh[nr * 72 + kb + 8 + (tig << 1)];
                mma_f16(sc[nt], qh[kt], b);
                mma_f16(sc[nt], ql[kt], b);
            }
        }
#pragma unroll
        for (int kt = 0; kt < 4; kt++) {
            const int kb = kt << 4;
#pragma unroll
            for (int nt = 0; nt < 4; nt++) {
                const int nr = (wn << 5) + (nt << 3) + g;
                unsigned b[2];
                b[0] = *(const unsigned*)&Kl[nr * 72 + kb + (tig << 1)];
                b[1] = *(const unsigned*)&Kl[nr * 72 + kb + 8 + (tig << 1)];
                mma_f16(sc[nt], qh[kt], b);
            }
        }

        float mx0 = -INFINITY, mx1 = -INFINITY;
#pragma unroll
        for (int nt = 0; nt < 4; nt++) {
            const int col = t0 + (wn << 5) + (nt << 3) + (tig << 1);
            if (causal) {
                if (col > row0)     sc[nt][0] = -INFINITY;
                if (col + 1 > row0) sc[nt][1] = -INFINITY;
                if (col > row1)     sc[nt][2] = -INFINITY;
                if (col + 1 > row1) sc[nt][3] = -INFINITY;
            }
            mx0 = fmaxf(mx0, fmaxf(sc[nt][0], sc[nt][1]));
            mx1 = fmaxf(mx1, fmaxf(sc[nt][2], sc[nt][3]));
        }
        mx0 = fmaxf(mx0, __shfl_xor_sync(0xffffffffu, mx0, 1));
        mx0 = fmaxf(mx0, __shfl_xor_sync(0xffffffffu, mx0, 2));
        mx1 = fmaxf(mx1, __shfl_xor_sync(0xffffffffu, mx1, 1));
        mx1 = fmaxf(mx1, __shfl_xor_sync(0xffffffffu, mx1, 2));
        smax[(wn << 6) + mrow] = mx0;
        smax[(wn << 6) + mrow + 8] = mx1;
        __syncthreads();

        const float mn0 = fmaxf(m0, fmaxf(smax[mrow], smax[64 + mrow]));
        const float mn1 = fmaxf(m1, fmaxf(smax[mrow + 8], smax[64 + mrow + 8]));
        const float cr0 = __expf(m0 - mn0);
        const float cr1 = __expf(m1 - mn1);
        m0 = mn0; m1 = mn1;
#pragma unroll
        for (int nt = 0; nt < 8; nt++) {
            o[nt][0] *= cr0; o[nt][1] *= cr0;
            o[nt][2] *= cr1; o[nt][3] *= cr1;
        }
        float p[4][4];
        float rs0 = 0.f, rs1 = 0.f;
#pragma unroll
        for (int nt = 0; nt < 4; nt++) {
            p[nt][0] = __expf(sc[nt][0] - mn0);
            p[nt][1] = __expf(sc[nt][1] - mn0);
            p[nt][2] = __expf(sc[nt][2] - mn1);
            p[nt][3] = __expf(sc[nt][3] - mn1);
            rs0 += p[nt][0] + p[nt][1];
            rs1 += p[nt][2] + p[nt][3];
        }
        rs0 += __shfl_xor_sync(0xffffffffu, rs0, 1);
        rs0 += __shfl_xor_sync(0xffffffffu, rs0, 2);
        rs1 += __shfl_xor_sync(0xffffffffu, rs1, 1);
        rs1 += __shfl_xor_sync(0xffffffffu, rs1, 2);
        ssum[(wn << 6) + mrow] = rs0;
        ssum[(wn << 6) + mrow + 8] = rs1;
        __syncthreads();
        l0 = l0 * cr0 + ssum[mrow] + ssum[64 + mrow];
        l1 = l1 * cr1 + ssum[mrow + 8] + ssum[64 + mrow + 8];

        unsigned ah[2][4], al[2][4];
#pragma unroll
        for (int kc = 0; kc < 2; kc++) {
            const int ta = kc << 1, tb = ta + 1;
            float h00 = __half2float(__float2half_rn(p[ta][0]));
            float h01 = __half2float(__float2half_rn(p[ta][1]));
            float h02 = __half2float(__float2half_rn(p[ta][2]));
            float h03 = __half2float(__float2half_rn(p[ta][3]));
            float h10 = __half2float(__float2half_rn(p[tb][0]));
            float h11 = __half2float(__float2half_rn(p[tb][1]));
            float h12 = __half2float(__float2half_rn(p[tb][2]));
            float h13 = __half2float(__float2half_rn(p[tb][3]));
            ah[kc][0] = pack_h2(h00, h01);
            ah[kc][1] = pack_h2(h02, h03);
            ah[kc][2] = pack_h2(h10, h11);
            ah[kc][3] = pack_h2(h12, h13);
            al[kc][0] = pack_h2(p[ta][0] - h00, p[ta][1] - h01);
            al[kc][1] = pack_h2(p[ta][2] - h02, p[ta][3] - h03);
            al[kc][2] = pack_h2(p[tb][0] - h10, p[tb][1] - h11);
            al[kc][3] = pack_h2(p[tb][2] - h12, p[tb][3] - h13);
        }

#pragma unroll
        for (int nt = 0; nt < 8; nt++) {
            const int dv = (nt << 3) + g;
            const int sw = ((dv >> 2) & 7) << 3;
            const int rb = dv * 72;
#pragma unroll
            for (int kc = 0; kc < 2; kc++) {
                const int kg = (wn << 5) + (kc << 4);
                unsigned vb[2], wb[2];
                vb[0] = *(const unsigned*)&Vh[rb + ((kg ^ sw) + (tig << 1))];
                vb[1] = *(const unsigned*)&Vh[rb + (((kg + 8) ^ sw) + (tig << 1))];
                mma_f16(o[nt], ah[kc], vb);
                mma_f16(o[nt], al[kc], vb);
                wb[0] = *(const unsigned*)&Vl[rb + ((kg ^ sw) + (tig << 1))];
                wb[1] = *(const unsigned*)&Vl[rb + (((kg + 8) ^ sw) + (tig << 1))];
                mma_f16(o[nt], ah[kc], wb);
            }
        }
    }

    const float il0 = 1.f / l0, il1 = 1.f / l1;
#pragma unroll
    for (int nt = 0; nt < 8; nt++) {
        o[nt][0] *= il0; o[nt][1] *= il0;
        o[nt][2] *= il1; o[nt][3] *= il1;
    }
    __syncthreads();
    float* po = sm_o + wn * 4608;
#pragma unroll
    for (int nt = 0; nt < 8; nt++) {
        const int dv = (nt << 3) + (tig << 1);
        *(float2*)&po[mrow * 72 + dv]       = make_float2(o[nt][0], o[nt][1]);
        *(float2*)&po[(mrow + 8) * 72 + dv] = make_float2(o[nt][2], o[nt][3]);
    }
    __syncthreads();
    if (wn == 0) {
        const int h = hb >> 2, b = hb & 3;
        const int r = lane >> 1;
        const int dvh = (lane & 1) << 5;
        const int row = (wm << 4) + r;
        const int s = s0 + row;
        const size_t orow = ((size_t)((h >> 2) * 1024 + (h & 3) * 256 + b * 64 + (s >> 4)) << 10)
                          + ((s & 15) << 6);
#pragma unroll
        for (int i = 0; i < 8; i++) {
            const int dv = dvh + (i << 2);
            float4 a = *(const float4*)&sm_o[row * 72 + dv];
            float4 bb = *(const float4*)&sm_o[4608 + row * 72 + dv];
            float4 vv = make_float4(a.x + bb.x, a.y + bb.y, a.z + bb.z, a.w + bb.w);
            *(float4*)(O2 + orow + dv) = vv;
        }
    }
}

// ---------------- LN finalize + apply ----------------------------------------
__global__ void ln_final_kernel()
{
    const int b = threadIdx.x;
    if (b < 4) {
        const double inv_n = 1.0 / 1048576.0;
        const double mean = g_bstat[b][0] * inv_n;
        const double var = g_bstat[b][1] * inv_n - mean * mean;
        g_stats[b][0] = (float)mean;
        g_stats[b][1] = (float)(1.0 / sqrt(var + 1e-5));
        g_bstat[b][0] = 0.0;
        g_bstat[b][1] = 0.0;
    }
}

__global__ void ln_apply_kernel(const float* __restrict__ X, const float* __restrict__ w,
                                const float* __restrict__ bb, float* __restrict__ Y)
{
    const size_t i = ((size_t)blockIdx.x * 256 + threadIdx.x) << 2;
    const int b = (int)(i >> 20);
    const float mean = g_stats[b][0], inv = g_stats[b][1];
    const size_t wi = i & 1048575;
    float4 x = *(const float4*)(X + i);
    float4 wv = *(const float4*)(w + wi);
    float4 bv = *(const float4*)(bb + wi);
    float4 y;
    y.x = (x.x - mean) * inv * wv.x + bv.x;
    y.y = (x.y - mean) * inv * wv.y + bv.y;
    y.z = (x.z - mean) * inv * wv.z + bv.z;
    y.w = (x.w - mean) * inv * wv.w + bv.w;
    *(float4*)(Y + i) = y;
}

// ---------------- driver -----------------------------------------------------
extern "C" void kernel_launch(void* const* d_in, const int* in_sizes, int n_in,
                              void* d_out, int out_size)
{
    const float* inputRes = (const float*)d_in[0];
    const float* outEnc   = (const float*)d_in[1];
    const float* ln1w = (const float*)d_in[10];
    const float* ln1b = (const float*)d_in[11];
    const float* ln2w = (const float*)d_in[12];
    const float* ln2b = (const float*)d_in[13];
    const float* ln3w = (const float*)d_in[14];
    const float* ln3b = (const float*)d_in[15];
    const float* W1 = (const float*)d_in[16];
    const float* b1 = (const float*)d_in[17];
    const float* W2 = (const float*)d_in[18];
    const float* b2 = (const float*)d_in[19];
    float* out = (float*)d_out;

    float *q, *kT, *v, *o2, *t1, *n1, *n2, *fc1;
    __half* ws;
    cudaGetSymbolAddress((void**)&q,   g_q);
    cudaGetSymbolAddress((void**)&kT,  g_kT);
    cudaGetSymbolAddress((void**)&v,   g_v);
    cudaGetSymbolAddress((void**)&o2,  g_o2);
    cudaGetSymbolAddress((void**)&t1,  g_t1);
    cudaGetSymbolAddress((void**)&n1,  g_n1);
    cudaGetSymbolAddress((void**)&n2,  g_n2);
    cudaGetSymbolAddress((void**)&fc1, g_fc1);
    cudaGetSymbolAddress((void**)&ws,  g_ws);

    const int FSM = 37888;
    cudaFuncSetAttribute(flash_mma_kernel, cudaFuncAttributeMaxDynamicSharedMemorySize, FSM);

    const int SMH = 81920;
    cudaFuncSetAttribute(hf_gemm_proj, cudaFuncAttributeMaxDynamicSharedMemorySize, SMH);
    cudaFuncSetAttribute(hf_gemm<false, true, false, true>, cudaFuncAttributeMaxDynamicSharedMemorySize, SMH);
    cudaFuncSetAttribute(hf_gemm<true, false, true, false>, cudaFuncAttributeMaxDynamicSharedMemorySize, SMH);
    cudaFuncSetAttribute(hf_gemm<true, true, false, true>, cudaFuncAttributeMaxDynamicSharedMemorySize, SMH);

    dim3 blk(256);

    // ---- pre-split weights + clear LN accumulators ----
    W8Pack pk;
    pk.w[0] = (const float*)d_in[2]; pk.w[1] = (const float*)d_in[3];
    pk.w[2] = (const float*)d_in[4]; pk.w[3] = (const float*)d_in[5];
    pk.w[4] = (const float*)d_in[6]; pk.w[5] = (const float*)d_in[7];
    pk.w[6] = (const float*)d_in[8]; pk.w[7] = (const float*)d_in[9];
    clear_stats_kernel<<<1, 32>>>();
    wsplit8_kernel<<<dim3(16, 16, 8), blk>>>(pk, ws);
    wsplit_kernel<<<dim3(32, 16), blk>>>(W1, ws + OFF_W1, 2048, 1024);
    wsplit_kernel<<<dim3(16, 32), blk>>>(W2, ws + OFF_W2, 1024, 2048);

    dim3 g1024(8, 32), g2048(16, 32);

    // ---- MHA1 (self, causal): fused QKV projection ----
    ProjPack p1;
    p1.j[0] = {ws + OFF_WQ1, q, 0};
    p1.j[1] = {ws + OFF_WK1, kT, 1};
    p1.j[2] = {ws + OFF_WV1, v, 0};
    hf_gemm_proj<<<dim3(8, 32, 3), blk, SMH>>>(outEnc, p1, 1024);
    flash_mma_kernel<<<dim3(16, 64), blk, FSM>>>(q, kT, v, o2, 1);
    hf_gemm<false, true, false, true><<<g1024, blk, SMH>>>(o2, ws + OFF_WO1, nullptr, outEnc, t1, 1024, 1024);
    ln_final_kernel<<<1, 32>>>();
    ln_apply_kernel<<<4096, blk>>>(t1, ln1w, ln1b, n1);

    // ---- MHA2 (cross): fused KV projection + Q projection ----
    ProjPack p2;
    p2.j[0] = {ws + OFF_WK2, kT, 1};
    p2.j[1] = {ws + OFF_WV2, v, 0};
    p2.j[2] = {nullptr, nullptr, 0};
    hf_gemm_proj<<<dim3(8, 32, 2), blk, SMH>>>(inputRes, p2, 1024);
    ProjPack p3;
    p3.j[0] = {ws + OFF_WQ2, q, 0};
    p3.j[1] = {nullptr, nullptr, 0};
    p3.j[2] = {nullptr, nullptr, 0};
    hf_gemm_proj<<<dim3(8, 32, 1), blk, SMH>>>(n1, p3, 1024);
    flash_mma_kernel<<<dim3(16, 64), blk, FSM>>>(q, kT, v, o2, 0);
    hf_gemm<false, true, false, true><<<g1024, blk, SMH>>>(o2, ws + OFF_WO2, nullptr, outEnc, t1, 1024, 1024);
    ln_final_kernel<<<1, 32>>>();
    ln_apply_kernel<<<4096, blk>>>(t1, ln2w, ln2b, n2);

    // ---- FFN ----
    hf_gemm<true, false, true, false><<<g2048, blk, SMH>>>(n2,  ws + OFF_W1, b1, nullptr, fc1, 2048, 1024);
    hf_gemm<true, true, false, true><<<g1024, blk, SMH>>>(fc1, ws + OFF_W2, b2, n2,      t1,  1024, 2048);
    ln_final_kernel<<<1, 32>>>();
    ln_apply_kernel<<<4096, blk>>>(t1, ln3w, ln3b, out);
}

// round 17
// speedup vs baseline: 1.0409x; 1.0148x over previous
#include <cuda_runtime.h>
#include <cuda_fp16.h>
#include <math.h>
#include <stdint.h>

#define N_ELEM 4194304  // 4*1024*1024

// ---------------- scratch (device globals) ----------------------------------
__device__ float  g_q [N_ELEM];
__device__ float  g_kT[N_ELEM];
__device__ float  g_v [N_ELEM];
__device__ float  g_o2[N_ELEM];
__device__ float  g_t1[N_ELEM];
__device__ float  g_n1[N_ELEM];
__device__ float  g_n2[N_ELEM];
__device__ float  g_fc1[4096 * 2048];
__device__ double g_bstat[4][2];   // {sum, sumsq} per batch
__device__ float  g_stats[4][2];   // {mean, invstd}
__device__ __align__(16) __half g_ws[25165824];  // weight planes [2][N][K]

#define OFF_WQ1 0
#define OFF_WK1 2097152
#define OFF_WV1 4194304
#define OFF_WO1 6291456
#define OFF_WQ2 8388608
#define OFF_WK2 10485760
#define OFF_WV2 12582912
#define OFF_WO2 14680064
#define OFF_W1  16777216
#define OFF_W2  20971520

// ---------------- PTX helpers -------------------------------------------------
__device__ __forceinline__ void mma_f16(float* c, const unsigned* a, const unsigned* b) {
    asm volatile(
        "mma.sync.aligned.m16n8k16.row.col.f32.f16.f16.f32 "
        "{%0,%1,%2,%3}, {%4,%5,%6,%7}, {%8,%9}, {%0,%1,%2,%3};\n"
        : "+f"(c[0]), "+f"(c[1]), "+f"(c[2]), "+f"(c[3])
        : "r"(a[0]), "r"(a[1]), "r"(a[2]), "r"(a[3]), "r"(b[0]), "r"(b[1]));
}
__device__ __forceinline__ unsigned pack_h2(float a, float b) {
    __half2 h = __floats2half2_rn(a, b);
    return *(unsigned*)&h;
}
__device__ __forceinline__ void ldsm4(unsigned* r, uint32_t a) {
    asm volatile("ldmatrix.sync.aligned.m8n8.x4.shared.b16 {%0,%1,%2,%3}, [%4];"
        : "=r"(r[0]), "=r"(r[1]), "=r"(r[2]), "=r"(r[3]) : "r"(a));
}
__device__ __forceinline__ void cp16(uint32_t dst, const void* src) {
    asm volatile("cp.async.cg.shared.global [%0], [%1], 16;" :: "r"(dst), "l"(src));
}
#define CP_COMMIT() asm volatile("cp.async.commit_group;" ::: "memory")
#define CP_WAIT0()  asm volatile("cp.async.wait_group 0;" ::: "memory")

// ---------------- weight transpose + 2-way fp16 split ------------------------
struct W8Pack { const float* w[8]; };

__device__ __forceinline__ void wsplit_body(const float* __restrict__ W,
                                            __half* __restrict__ out,
                                            int N, int K, bool proj,
                                            int n0, int k0, int tid)
{
    __shared__ float t[64][65];
#pragma unroll
    for (int r = 0; r < 4; r++) {
        const int flat = tid + (r << 8);
        const int kr = flat >> 4, nc = (flat & 15) << 2;
        const float* src;
        if (proj) src = W + ((size_t)((n0 + nc) >> 6) << 16) + ((size_t)(k0 + kr) << 6) + ((n0 + nc) & 63);
        else      src = W + (size_t)(k0 + kr) * N + n0 + nc;
        float4 v = *(const float4*)src;
        t[kr][nc] = v.x; t[kr][nc + 1] = v.y; t[kr][nc + 2] = v.z; t[kr][nc + 3] = v.w;
    }
    __syncthreads();
    const size_t ps = (size_t)N * K;
#pragma unroll
    for (int r = 0; r < 4; r++) {
        const int flat = tid + (r << 8);
        const int nr = flat >> 4, kc = (flat & 15) << 2;
        unsigned short u0[4], u1[4];
#pragma unroll
        for (int j = 0; j < 4; j++) {
            float x = t[kc + j][nr];
            __half h0 = __float2half_rn(x);
            float r1 = x - __half2float(h0);
            u0[j] = __half_as_ushort(h0);
            u1[j] = __half_as_ushort(__float2half_rn(r1));
        }
        const size_t dst = (size_t)(n0 + nr) * K + k0 + kc;
        *(uint2*)(out + dst)      = make_uint2(u0[0] | (u0[1] << 16), u0[2] | (u0[3] << 16));
        *(uint2*)(out + ps + dst) = make_uint2(u1[0] | (u1[1] << 16), u1[2] | (u1[3] << 16));
    }
}

__global__ __launch_bounds__(256)
void wsplit8_kernel(W8Pack pk, __half* __restrict__ out)
{
    const int z = blockIdx.z;
    const bool proj = (z & 3) != 3;
    wsplit_body(pk.w[z], out + (size_t)z * 2097152, 1024, 1024, proj,
                blockIdx.x << 6, blockIdx.y << 6, threadIdx.x);
}

__global__ __launch_bounds__(256)
void wsplit_kernel(const float* __restrict__ W, __half* __restrict__ out, int N, int K)
{
    wsplit_body(W, out, N, K, false, blockIdx.x << 6, blockIdx.y << 6, threadIdx.x);
}

__global__ void clear_stats_kernel()
{
    if (threadIdx.x < 8) ((double*)g_bstat)[threadIdx.x] = 0.0;
}

// ---------------- GEMM core (shared mainloop) ---------------------------------
struct ProjJob { const __half* Bp; float* C; int mode; };  // mode 0 std, 1 kT
struct ProjPack { ProjJob j[3]; };

__device__ __forceinline__ void gemm_mainloop(
    const float* __restrict__ A, const __half* __restrict__ Bp,
    __half* smp, uint32_t sbase, float acc[4][4][4],
    int m0, int n0, int N, int K, int tid, int wm, int wn, int aoff, int boff)
{
    const size_t bstride = (size_t)N * K;
    const int nstage = K >> 5;

    // ---- prologue: B(0) via cp.async, A(0) direct ----
#pragma unroll
    for (int p = 0; p < 2; p++)
#pragma unroll
        for (int r = 0; r < 2; r++) {
            const int flat = tid + (r << 8);
            const int row = flat >> 2, cs = (flat & 3) << 3;
            cp16(sbase + 20480 + p * 10240 + ((row * 40 + cs) << 1),
                 Bp + (size_t)p * bstride + (size_t)(n0 + row) * K + cs);
        }
    CP_COMMIT();
#pragma unroll
    for (int r = 0; r < 4; r++) {
        const int flat = tid + (r << 8);
        const int row = flat >> 3, c4 = (flat & 7) << 2;
        float4 av = *(const float4*)(A + (size_t)(m0 + row) * K + c4);
        float x[4] = {av.x, av.y, av.z, av.w};
        unsigned short u0[4], u1[4];
#pragma unroll
        for (int j = 0; j < 4; j++) {
            __half h0 = __float2half_rn(x[j]);
            float r1 = x[j] - __half2float(h0);
            u0[j] = __half_as_ushort(h0);
            u1[j] = __half_as_ushort(__float2half_rn(r1));
        }
        const int off = row * 40 + c4;
        *(uint2*)(smp + off)        = make_uint2(u0[0] | (u0[1] << 16), u0[2] | (u0[3] << 16));
        *(uint2*)(smp + 5120 + off) = make_uint2(u1[0] | (u1[1] << 16), u1[2] | (u1[3] << 16));
    }

    for (int s = 0; s < nstage; s++) {
        const uint32_t stg = (uint32_t)(s & 1) * 40960u;
        CP_WAIT0();
        __syncthreads();

        float4 pa2[4];
        const int kn = (s + 1) << 5;
        const bool more = kn < K;
        if (more) {
            const uint32_t nst = (uint32_t)((s + 1) & 1) * 40960u;
#pragma unroll
            for (int p = 0; p < 2; p++)
#pragma unroll
                for (int r = 0; r < 2; r++) {
                    const int flat = tid + (r << 8);
                    const int row = flat >> 2, cs = (flat & 3) << 3;
                    cp16(sbase + nst + 20480 + p * 10240 + ((row * 40 + cs) << 1),
                         Bp + (size_t)p * bstride + (size_t)(n0 + row) * K + kn + cs);
                }
            CP_COMMIT();
#pragma unroll
            for (int r = 0; r < 4; r++) {
                const int flat = tid + (r << 8);
                const int row = flat >> 3, c4 = (flat & 7) << 2;
                pa2[r] = *(const float4*)(A + (size_t)(m0 + row) * K + kn + c4);
            }
        }

        const uint32_t Ab = sbase + stg;
        const uint32_t Bb = sbase + stg + 20480;
#pragma unroll
        for (int kt = 0; kt < 2; kt++) {
            const int kbB = kt << 5;
            unsigned a0[4][4], b0[4][2], bx[4][2], a1[4][4];
#pragma unroll
            for (int mt = 0; mt < 4; mt++)
                ldsm4(a0[mt], Ab + ((((wm << 6) + (mt << 4)) * 40) << 1) + kbB + aoff);
#pragma unroll
            for (int nh = 0; nh < 2; nh++) {
                unsigned t4[4];
                ldsm4(t4, Bb + ((((wn << 5) + (nh << 4)) * 40) << 1) + kbB + boff);
                b0[2 * nh][0] = t4[0]; b0[2 * nh][1] = t4[1];
                b0[2 * nh + 1][0] = t4[2]; b0[2 * nh + 1][1] = t4[3];
            }
#pragma unroll
            for (int mt = 0; mt < 4; mt++)
#pragma unroll
                for (int nt = 0; nt < 4; nt++)
                    mma_f16(acc[mt][nt], a0[mt], b0[nt]);   // Ah*Bh
#pragma unroll
            for (int nh = 0; nh < 2; nh++) {
                unsigned t4[4];
                ldsm4(t4, Bb + 10240 + ((((wn << 5) + (nh << 4)) * 40) << 1) + kbB + boff);
                bx[2 * nh][0] = t4[0]; bx[2 * nh][1] = t4[1];
                bx[2 * nh + 1][0] = t4[2]; bx[2 * nh + 1][1] = t4[3];
            }
#pragma unroll
            for (int mt = 0; mt < 4; mt++)
#pragma unroll
                for (int nt = 0; nt < 4; nt++)
                    mma_f16(acc[mt][nt], a0[mt], bx[nt]);   // Ah*Bl
#pragma unroll
            for (int mt = 0; mt < 4; mt++)
                ldsm4(a1[mt], Ab + 10240 + ((((wm << 6) + (mt << 4)) * 40) << 1) + kbB + aoff);
#pragma unroll
            for (int mt = 0; mt < 4; mt++)
#pragma unroll
                for (int nt = 0; nt < 4; nt++)
                    mma_f16(acc[mt][nt], a1[mt], b0[nt]);   // Al*Bh
        }

        if (more) {
            __half* An = smp + ((s + 1) & 1) * 20480;
#pragma unroll
            for (int r = 0; r < 4; r++) {
                const int flat = tid + (r << 8);
                const int row = flat >> 3, c4 = (flat & 7) << 2;
                float x[4] = {pa2[r].x, pa2[r].y, pa2[r].z, pa2[r].w};
                unsigned short u0[4], u1[4];
#pragma unroll
                for (int j = 0; j < 4; j++) {
                    __half h0 = __float2half_rn(x[j]);
                    float r1 = x[j] - __half2float(h0);
                    u0[j] = __half_as_ushort(h0);
                    u1[j] = __half_as_ushort(__float2half_rn(r1));
                }
                const int off = row * 40 + c4;
                *(uint2*)(An + off)        = make_uint2(u0[0] | (u0[1] << 16), u0[2] | (u0[3] << 16));
                *(uint2*)(An + 5120 + off) = make_uint2(u1[0] | (u1[1] << 16), u1[2] | (u1[3] << 16));
            }
        }
    }
}

// ---------------- fused multi-projection GEMM (z selects weight/output) ------
__global__ __launch_bounds__(256, 2)
void hf_gemm_proj(const float* __restrict__ A, ProjPack pk, int K)
{
    extern __shared__ __half smp[];
    const uint32_t sbase = (uint32_t)__cvta_generic_to_shared(smp);
    const int tid  = threadIdx.x;
    const int lane = tid & 31, wid = tid >> 5;
    const int g = lane >> 2, tig = lane & 3;
    const int quad = lane >> 3, rr = lane & 7;
    const int wm = wid >> 2, wn = wid & 3;
    const int m0 = blockIdx.y << 7, n0 = blockIdx.x << 7;
    const int aoff = ((rr + ((quad & 1) << 3)) * 40 + ((quad >> 1) << 3)) << 1;
    const int boff = ((rr + ((quad >> 1) << 3)) * 40 + ((quad & 1) << 3)) << 1;
    const ProjJob job = pk.j[blockIdx.z];

    float acc[4][4][4];
#pragma unroll
    for (int mt = 0; mt < 4; mt++)
#pragma unroll
        for (int nt = 0; nt < 4; nt++)
#pragma unroll
            for (int c = 0; c < 4; c++) acc[mt][nt][c] = 0.f;

    gemm_mainloop(A, job.Bp, smp, sbase, acc, m0, n0, 1024, K, tid, wm, wn, aoff, boff);

    float* C = job.C;
    if (job.mode == 0) {
#pragma unroll
        for (int mt = 0; mt < 4; mt++)
#pragma unroll
            for (int nt = 0; nt < 4; nt++) {
                const int m = m0 + (wm << 6) + (mt << 4) + g;
                const int n = n0 + (wn << 5) + (nt << 3) + (tig << 1);
                const float* c = acc[mt][nt];
                const int b = m >> 10, s = m & 1023;
                const int h = n >> 6, d = n & 63;
                const size_t hb = (size_t)(h * 4 + b);
                *(float2*)(C + (((hb << 10) + s) << 6) + d) = make_float2(c[0], c[1]);
                *(float2*)(C + (((hb << 10) + s + 8) << 6) + d) = make_float2(c[2], c[3]);
            }
    } else {
#pragma unroll
        for (int mt = 0; mt < 4; mt++)
#pragma unroll
            for (int nt = 0; nt < 4; nt++) {
                const int m = m0 + (wm << 6) + (mt << 4) + g;
                const int n = n0 + (wn << 5) + (nt << 3) + (tig << 1);
                const float* c = acc[mt][nt];
                const int b = m >> 10, s = m & 1023;
                const int h = n >> 6, d = n & 63;
                const size_t hb = (size_t)(h * 4 + b);
                const int t0a = ((s & 15) << 6) | d;
                const int t0b = (((s + 8) & 15) << 6) | d;
                C[((hb << 10) + t0a)     * 64 + (s >> 4)]       = c[0];
                C[((hb << 10) + t0a + 1) * 64 + (s >> 4)]       = c[1];
                C[((hb << 10) + t0b)     * 64 + ((s + 8) >> 4)] = c[2];
                C[((hb << 10) + t0b + 1) * 64 + ((s + 8) >> 4)] = c[3];
            }
    }
}

// ---------------- generic GEMM (row-major out, +bias/res/relu, +LN stats) ----
template<bool BIAS, bool RES, bool RELU, bool LNST>
__global__ __launch_bounds__(256, 2)
void hf_gemm(const float* __restrict__ A, const __half* __restrict__ Bp,
             const float* __restrict__ bias, const float* __restrict__ res,
             float* __restrict__ C, int N, int K)
{
    extern __shared__ __half smp[];
    const uint32_t sbase = (uint32_t)__cvta_generic_to_shared(smp);
    const int tid  = threadIdx.x;
    const int lane = tid & 31, wid = tid >> 5;
    const int g = lane >> 2, tig = lane & 3;
    const int quad = lane >> 3, rr = lane & 7;
    const int wm = wid >> 2, wn = wid & 3;
    const int m0 = blockIdx.y << 7, n0 = blockIdx.x << 7;
    const int aoff = ((rr + ((quad & 1) << 3)) * 40 + ((quad >> 1) << 3)) << 1;
    const int boff = ((rr + ((quad >> 1) << 3)) * 40 + ((quad & 1) << 3)) << 1;

    float acc[4][4][4];
#pragma unroll
    for (int mt = 0; mt < 4; mt++)
#pragma unroll
        for (int nt = 0; nt < 4; nt++)
#pragma unroll
            for (int c = 0; c < 4; c++) acc[mt][nt][c] = 0.f;

    gemm_mainloop(A, Bp, smp, sbase, acc, m0, n0, N, K, tid, wm, wn, aoff, boff);

    float ls = 0.f, lq = 0.f;
#pragma unroll
    for (int mt = 0; mt < 4; mt++) {
#pragma unroll
        for (int nt = 0; nt < 4; nt++) {
            const int m = m0 + (wm << 6) + (mt << 4) + g;
            const int n = n0 + (wn << 5) + (nt << 3) + (tig << 1);
            const float* c = acc[mt][nt];
            float2 v0 = make_float2(c[0], c[1]);
            float2 v1 = make_float2(c[2], c[3]);
            if (BIAS) {
                float2 bv = *(const float2*)(bias + n);
                v0.x += bv.x; v0.y += bv.y; v1.x += bv.x; v1.y += bv.y;
            }
            if (RES) {
                float2 r0 = *(const float2*)(res + (size_t)m * N + n);
                float2 r1 = *(const float2*)(res + (size_t)(m + 8) * N + n);
                v0.x += r0.x; v0.y += r0.y; v1.x += r1.x; v1.y += r1.y;
            }
            if (RELU) {
                v0.x = fmaxf(v0.x, 0.f); v0.y = fmaxf(v0.y, 0.f);
                v1.x = fmaxf(v1.x, 0.f); v1.y = fmaxf(v1.y, 0.f);
            }
            if (LNST) {
                ls += v0.x + v0.y + v1.x + v1.y;
                lq += v0.x * v0.x + v0.y * v0.y + v1.x * v1.x + v1.y * v1.y;
            }
            *(float2*)(C + (size_t)m * N + n) = v0;
            *(float2*)(C + (size_t)(m + 8) * N + n) = v1;
        }
    }

    if constexpr (LNST) {
        __syncthreads();
        double* sd = (double*)smp;
        double* sq = sd + 256;
        sd[tid] = (double)ls;
        sq[tid] = (double)lq;
        __syncthreads();
        for (int off = 128; off > 0; off >>= 1) {
            if (tid < off) { sd[tid] += sd[tid + off]; sq[tid] += sq[tid + off]; }
            __syncthreads();
        }
        if (tid == 0) {
            const int b = m0 >> 10;
            atomicAdd(&g_bstat[b][0], sd[0]);
            atomicAdd(&g_bstat[b][1], sq[0]);
        }
    }
}

// ---------------- tensor-core flash attention --------------------------------
// causal path uses LPT ordering: heaviest s-tiles scheduled first.
__global__ __launch_bounds__(256)
void flash_mma_kernel(const float* __restrict__ Q, const float* __restrict__ KT,
                      const float* __restrict__ V, float* __restrict__ O2, int causal)
{
    extern __shared__ char fsm[];
    __half* Kh = (__half*)fsm;
    __half* Kl = Kh + 4608;
    __half* Vh = Kh + 9216;
    __half* Vl = Kh + 13824;
    float* smax = (float*)(fsm + 36864);
    float* ssum = smax + 128;
    float* sm_o = (float*)fsm;

    const int tid = threadIdx.x;
    const int lane = tid & 31, wid = tid >> 5;
    const int g = lane >> 2, tig = lane & 3;
    const int wm = wid >> 1, wn = wid & 1;
    const int sblk = causal ? (15 - (int)blockIdx.x) : (int)blockIdx.x;
    const int s0 = sblk << 6;
    const int hb = blockIdx.y;
    const size_t base = (size_t)hb << 16;
    const int mrow = (wm << 4) + g;

#pragma unroll
    for (int it = 0; it < 4; it++) {
        const int flat = tid + (it << 8);
        const int r = flat >> 4, c4 = (flat & 15) << 2;
        float4 qv = *(const float4*)(Q + base + ((size_t)(s0 + r) << 6) + c4);
        float x[4] = {qv.x * 0.125f, qv.y * 0.125f, qv.z * 0.125f, qv.w * 0.125f};
        unsigned short u0[4], u1[4];
#pragma unroll
        for (int j = 0; j < 4; j++) {
            __half h0 = __float2half_rn(x[j]);
            float r1 = x[j] - __half2float(h0);
            u0[j] = __half_as_ushort(h0);
            u1[j] = __half_as_ushort(__float2half_rn(r1));
        }
        *(uint2*)&Kh[r * 72 + c4] = make_uint2(u0[0] | (u0[1] << 16), u0[2] | (u0[3] << 16));
        *(uint2*)&Kl[r * 72 + c4] = make_uint2(u1[0] | (u1[1] << 16), u1[2] | (u1[3] << 16));
    }
    __syncthreads();

    unsigned qh[4][4], ql[4][4];
#pragma unroll
    for (int kt = 0; kt < 4; kt++) {
        const int kb = kt << 4;
        qh[kt][0] = *(const unsigned*)&Kh[mrow * 72 + kb + (tig << 1)];
        qh[kt][1] = *(const unsigned*)&Kh[(mrow + 8) * 72 + kb + (tig << 1)];
        qh[kt][2] = *(const unsigned*)&Kh[mrow * 72 + kb + 8 + (tig << 1)];
        qh[kt][3] = *(const unsigned*)&Kh[(mrow + 8) * 72 + kb + 8 + (tig << 1)];
        ql[kt][0] = *(const unsigned*)&Kl[mrow * 72 + kb + (tig << 1)];
        ql[kt][1] = *(const unsigned*)&Kl[(mrow + 8) * 72 + kb + (tig << 1)];
        ql[kt][2] = *(const unsigned*)&Kl[mrow * 72 + kb + 8 + (tig << 1)];
        ql[kt][3] = *(const unsigned*)&Kl[(mrow + 8) * 72 + kb + 8 + (tig << 1)];
    }

    float o[8][4];
#pragma unroll
    for (int nt = 0; nt < 8; nt++)
#pragma unroll
        for (int c = 0; c < 4; c++) o[nt][c] = 0.f;
    float m0 = -INFINITY, m1 = -INFINITY, l0 = 0.f, l1 = 0.f;

    const int row0 = s0 + mrow, row1 = row0 + 8;
    const int ntiles = causal ? (sblk + 1) : 16;

    for (int jt = 0; jt < ntiles; jt++) {
        const int t0 = jt << 6;
        __syncthreads();

#pragma unroll
        for (int it = 0; it < 4; it++) {
            const int flat = tid + (it << 8);
            const int r = flat >> 4, c4 = (flat & 15) << 2;
            float4 kv = *(const float4*)(KT + base + ((size_t)(t0 + r) << 6) + c4);
            float x[4] = {kv.x, kv.y, kv.z, kv.w};
            unsigned short u0[4], u1[4];
#pragma unroll
            for (int j = 0; j < 4; j++) {
                __half h0 = __float2half_rn(x[j]);
                float r1 = x[j] - __half2float(h0);
                u0[j] = __half_as_ushort(h0);
                u1[j] = __half_as_ushort(__float2half_rn(r1));
            }
            *(uint2*)&Kh[r * 72 + c4] = make_uint2(u0[0] | (u0[1] << 16), u0[2] | (u0[3] << 16));
            *(uint2*)&Kl[r * 72 + c4] = make_uint2(u1[0] | (u1[1] << 16), u1[2] | (u1[3] << 16));
        }
#pragma unroll
        for (int it = 0; it < 4; it++) {
            const int flat = tid + (it << 8);
            const int tr = flat >> 4, dv4 = (flat & 15) << 2;
            float4 vv = *(const float4*)(V + base + ((size_t)(t0 + tr) << 6) + dv4);
            float x[4] = {vv.x, vv.y, vv.z, vv.w};
#pragma unroll
            for (int j = 0; j < 4; j++) {
                const int dv = dv4 + j;
                const int sw = ((dv >> 2) & 7) << 3;
                const int idx = dv * 72 + (tr ^ sw);
                __half h0 = __float2half_rn(x[j]);
                float r1 = x[j] - __half2float(h0);
                Vh[idx] = h0;
                Vl[idx] = __float2half_rn(r1);
            }
        }
        __syncthreads();

        float sc[4][4];
#pragma unroll
        for (int nt = 0; nt < 4; nt++)
#pragma unroll
            for (int c = 0; c < 4; c++) sc[nt][c] = 0.f;
#pragma unroll
        for (int kt = 0; kt < 4; kt++) {
            const int kb = kt << 4;
#pragma unroll
            for (int nt = 0; nt < 4; nt++) {
                const int nr = (wn << 5) + (nt << 3) + g;
                unsigned b[2];
                b[0] = *(const unsigned*)&Kh[nr * 72 + kb + (tig << 1)];
                b[1] = *(const unsigned*)&Kh[nr * 72 + kb + 8 + (tig << 1)];
                mma_f16(sc[nt], qh[kt], b);
                mma_f16(sc[nt], ql[kt], b);
            }
        }
#pragma unroll
        for (int kt = 0; kt < 4; kt++) {
            const int kb = kt << 4;
#pragma unroll
            for (int nt = 0; nt < 4; nt++) {
                const int nr = (wn << 5) + (nt << 3) + g;
                unsigned b[2];
                b[0] = *(const unsigned*)&Kl[nr * 72 + kb + (tig << 1)];
                b[1] = *(const unsigned*)&Kl[nr * 72 + kb + 8 + (tig << 1)];
                mma_f16(sc[nt], qh[kt], b);
            }
        }

        float mx0 = -INFINITY, mx1 = -INFINITY;
#pragma unroll
        for (int nt = 0; nt < 4; nt++) {
            const int col = t0 + (wn << 5) + (nt << 3) + (tig << 1);
            if (causal) {
                if (col > row0)     sc[nt][0] = -INFINITY;
                if (col + 1 > row0) sc[nt][1] = -INFINITY;
                if (col > row1)     sc[nt][2] = -INFINITY;
                if (col + 1 > row1) sc[nt][3] = -INFINITY;
            }
            mx0 = fmaxf(mx0, fmaxf(sc[nt][0], sc[nt][1]));
            mx1 = fmaxf(mx1, fmaxf(sc[nt][2], sc[nt][3]));
        }
        mx0 = fmaxf(mx0, __shfl_xor_sync(0xffffffffu, mx0, 1));
        mx0 = fmaxf(mx0, __shfl_xor_sync(0xffffffffu, mx0, 2));
        mx1 = fmaxf(mx1, __shfl_xor_sync(0xffffffffu, mx1, 1));
        mx1 = fmaxf(mx1, __shfl_xor_sync(0xffffffffu, mx1, 2));
        smax[(wn << 6) + mrow] = mx0;
        smax[(wn << 6) + mrow + 8] = mx1;
        __syncthreads();

        const float mn0 = fmaxf(m0, fmaxf(smax[mrow], smax[64 + mrow]));
        const float mn1 = fmaxf(m1, fmaxf(smax[mrow + 8], smax[64 + mrow + 8]));
        const float cr0 = __expf(m0 - mn0);
        const float cr1 = __expf(m1 - mn1);
        m0 = mn0; m1 = mn1;
#pragma unroll
        for (int nt = 0; nt < 8; nt++) {
            o[nt][0] *= cr0; o[nt][1] *= cr0;
            o[nt][2] *= cr1; o[nt][3] *= cr1;
        }
        float p[4][4];
        float rs0 = 0.f, rs1 = 0.f;
#pragma unroll
        for (int nt = 0; nt < 4; nt++) {
            p[nt][0] = __expf(sc[nt][0] - mn0);
            p[nt][1] = __expf(sc[nt][1] - mn0);
            p[nt][2] = __expf(sc[nt][2] - mn1);
            p[nt][3] = __expf(sc[nt][3] - mn1);
            rs0 += p[nt][0] + p[nt][1];
            rs1 += p[nt][2] + p[nt][3];
        }
        rs0 += __shfl_xor_sync(0xffffffffu, rs0, 1);
        rs0 += __shfl_xor_sync(0xffffffffu, rs0, 2);
        rs1 += __shfl_xor_sync(0xffffffffu, rs1, 1);
        rs1 += __shfl_xor_sync(0xffffffffu, rs1, 2);
        ssum[(wn << 6) + mrow] = rs0;
        ssum[(wn << 6) + mrow + 8] = rs1;
        __syncthreads();
        l0 = l0 * cr0 + ssum[mrow] + ssum[64 + mrow];
        l1 = l1 * cr1 + ssum[mrow + 8] + ssum[64 + mrow + 8];

        unsigned ah[2][4], al[2][4];
#pragma unroll
        for (int kc = 0; kc < 2; kc++) {
            const int ta = kc << 1, tb = ta + 1;
            float h00 = __half2float(__float2half_rn(p[ta][0]));
            float h01 = __half2float(__float2half_rn(p[ta][1]));
            float h02 = __half2float(__float2half_rn(p[ta][2]));
            float h03 = __half2float(__float2half_rn(p[ta][3]));
            float h10 = __half2float(__float2half_rn(p[tb][0]));
            float h11 = __half2float(__float2half_rn(p[tb][1]));
            float h12 = __half2float(__float2half_rn(p[tb][2]));
            float h13 = __half2float(__float2half_rn(p[tb][3]));
            ah[kc][0] = pack_h2(h00, h01);
            ah[kc][1] = pack_h2(h02, h03);
            ah[kc][2] = pack_h2(h10, h11);
            ah[kc][3] = pack_h2(h12, h13);
            al[kc][0] = pack_h2(p[ta][0] - h00, p[ta][1] - h01);
            al[kc][1] = pack_h2(p[ta][2] - h02, p[ta][3] - h03);
            al[kc][2] = pack_h2(p[tb][0] - h10, p[tb][1] - h11);
            al[kc][3] = pack_h2(p[tb][2] - h12, p[tb][3] - h13);
        }

#pragma unroll
        for (int nt = 0; nt < 8; nt++) {
            const int dv = (nt << 3) + g;
            const int sw = ((dv >> 2) & 7) << 3;
            const int rb = dv * 72;
#pragma unroll
            for (int kc = 0; kc < 2; kc++) {
                const int kg = (wn << 5) + (kc << 4);
                unsigned vb[2], wb[2];
                vb[0] = *(const unsigned*)&Vh[rb + ((kg ^ sw) + (tig << 1))];
                vb[1] = *(const unsigned*)&Vh[rb + (((kg + 8) ^ sw) + (tig << 1))];
                mma_f16(o[nt], ah[kc], vb);
                mma_f16(o[nt], al[kc], vb);
                wb[0] = *(const unsigned*)&Vl[rb + ((kg ^ sw) + (tig << 1))];
                wb[1] = *(const unsigned*)&Vl[rb + (((kg + 8) ^ sw) + (tig << 1))];
                mma_f16(o[nt], ah[kc], wb);
            }
        }
    }

    const float il0 = 1.f / l0, il1 = 1.f / l1;
#pragma unroll
    for (int nt = 0; nt < 8; nt++) {
        o[nt][0] *= il0; o[nt][1] *= il0;
        o[nt][2] *= il1; o[nt][3] *= il1;
    }
    __syncthreads();
    float* po = sm_o + wn * 4608;
#pragma unroll
    for (int nt = 0; nt < 8; nt++) {
        const int dv = (nt << 3) + (tig << 1);
        *(float2*)&po[mrow * 72 + dv]       = make_float2(o[nt][0], o[nt][1]);
        *(float2*)&po[(mrow + 8) * 72 + dv] = make_float2(o[nt][2], o[nt][3]);
    }
    __syncthreads();
    if (wn == 0) {
        const int h = hb >> 2, b = hb & 3;
        const int r = lane >> 1;
        const int dvh = (lane & 1) << 5;
        const int row = (wm << 4) + r;
        const int s = s0 + row;
        const size_t orow = ((size_t)((h >> 2) * 1024 + (h & 3) * 256 + b * 64 + (s >> 4)) << 10)
                          + ((s & 15) << 6);
#pragma unroll
        for (int i = 0; i < 8; i++) {
            const int dv = dvh + (i << 2);
            float4 a = *(const float4*)&sm_o[row * 72 + dv];
            float4 bb = *(const float4*)&sm_o[4608 + row * 72 + dv];
            float4 vv = make_float4(a.x + bb.x, a.y + bb.y, a.z + bb.z, a.w + bb.w);
            *(float4*)(O2 + orow + dv) = vv;
        }
    }
}

// ---------------- LN finalize + apply ----------------------------------------
__global__ void ln_final_kernel()
{
    const int b = threadIdx.x;
    if (b < 4) {
        const double inv_n = 1.0 / 1048576.0;
        const double mean = g_bstat[b][0] * inv_n;
        const double var = g_bstat[b][1] * inv_n - mean * mean;
        g_stats[b][0] = (float)mean;
        g_stats[b][1] = (float)(1.0 / sqrt(var + 1e-5));
        g_bstat[b][0] = 0.0;
        g_bstat[b][1] = 0.0;
    }
}

__global__ void ln_apply_kernel(const float* __restrict__ X, const float* __restrict__ w,
                                const float* __restrict__ bb, float* __restrict__ Y)
{
    const size_t i = ((size_t)blockIdx.x * 256 + threadIdx.x) << 2;
    const int b = (int)(i >> 20);
    const float mean = g_stats[b][0], inv = g_stats[b][1];
    const size_t wi = i & 1048575;
    float4 x = *(const float4*)(X + i);
    float4 wv = *(const float4*)(w + wi);
    float4 bv = *(const float4*)(bb + wi);
    float4 y;
    y.x = (x.x - mean) * inv * wv.x + bv.x;
    y.y = (x.y - mean) * inv * wv.y + bv.y;
    y.z = (x.z - mean) * inv * wv.z + bv.z;
    y.w = (x.w - mean) * inv * wv.w + bv.w;
    *(float4*)(Y + i) = y;
}

// ---------------- driver -----------------------------------------------------
extern "C" void kernel_launch(void* const* d_in, const int* in_sizes, int n_in,
                              void* d_out, int out_size)
{
    const float* inputRes = (const float*)d_in[0];
    const float* outEnc   = (const float*)d_in[1];
    const float* ln1w = (const float*)d_in[10];
    const float* ln1b = (const float*)d_in[11];
    const float* ln2w = (const float*)d_in[12];
    const float* ln2b = (const float*)d_in[13];
    const float* ln3w = (const float*)d_in[14];
    const float* ln3b = (const float*)d_in[15];
    const float* W1 = (const float*)d_in[16];
    const float* b1 = (const float*)d_in[17];
    const float* W2 = (const float*)d_in[18];
    const float* b2 = (const float*)d_in[19];
    float* out = (float*)d_out;

    float *q, *kT, *v, *o2, *t1, *n1, *n2, *fc1;
    __half* ws;
    cudaGetSymbolAddress((void**)&q,   g_q);
    cudaGetSymbolAddress((void**)&kT,  g_kT);
    cudaGetSymbolAddress((void**)&v,   g_v);
    cudaGetSymbolAddress((void**)&o2,  g_o2);
    cudaGetSymbolAddress((void**)&t1,  g_t1);
    cudaGetSymbolAddress((void**)&n1,  g_n1);
    cudaGetSymbolAddress((void**)&n2,  g_n2);
    cudaGetSymbolAddress((void**)&fc1, g_fc1);
    cudaGetSymbolAddress((void**)&ws,  g_ws);

    const int FSM = 37888;
    cudaFuncSetAttribute(flash_mma_kernel, cudaFuncAttributeMaxDynamicSharedMemorySize, FSM);

    const int SMH = 81920;
    cudaFuncSetAttribute(hf_gemm_proj, cudaFuncAttributeMaxDynamicSharedMemorySize, SMH);
    cudaFuncSetAttribute(hf_gemm<false, true, false, true>, cudaFuncAttributeMaxDynamicSharedMemorySize, SMH);
    cudaFuncSetAttribute(hf_gemm<true, false, true, false>, cudaFuncAttributeMaxDynamicSharedMemorySize, SMH);
    cudaFuncSetAttribute(hf_gemm<true, true, false, true>, cudaFuncAttributeMaxDynamicSharedMemorySize, SMH);

    dim3 blk(256);

    // ---- pre-split weights + clear LN accumulators ----
    W8Pack pk;
    pk.w[0] = (const float*)d_in[2]; pk.w[1] = (const float*)d_in[3];
    pk.w[2] = (const float*)d_in[4]; pk.w[3] = (const float*)d_in[5];
    pk.w[4] = (const float*)d_in[6]; pk.w[5] = (const float*)d_in[7];
    pk.w[6] = (const float*)d_in[8]; pk.w[7] = (const float*)d_in[9];
    clear_stats_kernel<<<1, 32>>>();
    wsplit8_kernel<<<dim3(16, 16, 8), blk>>>(pk, ws);
    wsplit_kernel<<<dim3(32, 16), blk>>>(W1, ws + OFF_W1, 2048, 1024);
    wsplit_kernel<<<dim3(16, 32), blk>>>(W2, ws + OFF_W2, 1024, 2048);

    dim3 g1024(8, 32), g2048(16, 32);

    // ---- MHA1 (self, causal): fused QKV projection ----
    ProjPack p1;
    p1.j[0] = {ws + OFF_WQ1, q, 0};
    p1.j[1] = {ws + OFF_WK1, kT, 1};
    p1.j[2] = {ws + OFF_WV1, v, 0};
    hf_gemm_proj<<<dim3(8, 32, 3), blk, SMH>>>(outEnc, p1, 1024);
    flash_mma_kernel<<<dim3(16, 64), blk, FSM>>>(q, kT, v, o2, 1);
    hf_gemm<false, true, false, true><<<g1024, blk, SMH>>>(o2, ws + OFF_WO1, nullptr, outEnc, t1, 1024, 1024);
    ln_final_kernel<<<1, 32>>>();
    ln_apply_kernel<<<4096, blk>>>(t1, ln1w, ln1b, n1);

    // ---- MHA2 (cross): fused KV projection + Q projection ----
    ProjPack p2;
    p2.j[0] = {ws + OFF_WK2, kT, 1};
    p2.j[1] = {ws + OFF_WV2, v, 0};
    p2.j[2] = {nullptr, nullptr, 0};
    hf_gemm_proj<<<dim3(8, 32, 2), blk, SMH>>>(inputRes, p2, 1024);
    ProjPack p3;
    p3.j[0] = {ws + OFF_WQ2, q, 0};
    p3.j[1] = {nullptr, nullptr, 0};
    p3.j[2] = {nullptr, nullptr, 0};
    hf_gemm_proj<<<dim3(8, 32, 1), blk, SMH>>>(n1, p3, 1024);
    flash_mma_kernel<<<dim3(16, 64), blk, FSM>>>(q, kT, v, o2, 0);
    hf_gemm<false, true, false, true><<<g1024, blk, SMH>>>(o2, ws + OFF_WO2, nullptr, outEnc, t1, 1024, 1024);
    ln_final_kernel<<<1, 32>>>();
    ln_apply_kernel<<<4096, blk>>>(t1, ln2w, ln2b, n2);

    // ---- FFN ----
    hf_gemm<true, false, true, false><<<g2048, blk, SMH>>>(n2,  ws + OFF_W1, b1, nullptr, fc1, 2048, 1024);
    hf_gemm<true, true, false, true><<<g1024, blk, SMH>>>(fc1, ws + OFF_W2, b2, n2,      t1,  1024, 2048);
    ln_final_kernel<<<1, 32>>>();
    ln_apply_kernel<<<4096, blk>>>(t1, ln3w, ln3b, out);
}